// round 7
// baseline (speedup 1.0000x reference)
#include <cuda_runtime.h>
#include <math.h>
#include <stdint.h>

// ----------------------------- problem constants ---------------------------
#define CC   768
#define TT   1024
#define BBATCH 4
#define MM   (BBATCH*TT)
#define NHD  24
#define HSZ  32
#define HP_  32
#define WP_  32
#define C4   (CC/4)
#define CL   32

#define SSLOT 3145728ull
__device__ float g_scratch[16ull*SSLOT];

enum { EP_NONE = 0, EP_TANH = 1, EP_SILU = 2, EP_EXPW = 3, EP_MIX = 4 };

// ----------------------------- TF32 helpers --------------------------------
__device__ __forceinline__ float f2tf32(float x) {
    uint32_t r;
    asm("cvt.rna.tf32.f32 %0, %1;" : "=r"(r) : "f"(x));
    return __uint_as_float(r);
}

__device__ __forceinline__ void mma_tf32(float acc[4], const uint32_t a[4],
                                         const uint32_t b0, const uint32_t b1) {
    asm volatile(
        "mma.sync.aligned.m16n8k8.row.col.f32.tf32.tf32.f32 "
        "{%0,%1,%2,%3}, {%4,%5,%6,%7}, {%8,%9}, {%0,%1,%2,%3};"
        : "+f"(acc[0]), "+f"(acc[1]), "+f"(acc[2]), "+f"(acc[3])
        : "r"(a[0]), "r"(a[1]), "r"(a[2]), "r"(a[3]), "r"(b0), "r"(b1));
}

#define LDSM4(d0, d1, d2, d3, addr)                                           \
    asm volatile("ldmatrix.sync.aligned.m8n8.x4.shared.b16 {%0,%1,%2,%3}, [%4];" \
                 : "=r"(d0), "=r"(d1), "=r"(d2), "=r"(d3) : "r"(addr));

__device__ __forceinline__ void cpasync16(uint32_t saddr, const void* gptr) {
    asm volatile("cp.async.cg.shared.global [%0], [%1], 16;"
                 :: "r"(saddr), "l"(gptr));
}

// --------------------- weight transpose + tf32 pre-round --------------------
#define NTR 13
struct TArgs {
    const float* src[NTR];
    float*       dst[NTR];
    int K[NTR];
    int N[NTR];
    int Np[NTR];
};

__global__ void transpose_kernel(TArgs ta)
{
    __shared__ float tile[32][33];
    const int z = blockIdx.z;
    const int K = ta.K[z], N = ta.N[z], Np = ta.Np[z];
    const int x0 = blockIdx.x * 32;
    const int y0 = blockIdx.y * 32;
    if (x0 >= Np || y0 >= K) return;
    const float* src = ta.src[z];
    float* dst = ta.dst[z];
    const int tx = threadIdx.x, ty = threadIdx.y;
#pragma unroll
    for (int j = 0; j < 4; j++) {
        int k = y0 + ty + 8 * j;
        int n = x0 + tx;
        float v = (n < N) ? src[(size_t)k * N + n] : 0.f;
        tile[ty + 8 * j][tx] = f2tf32(v);
    }
    __syncthreads();
#pragma unroll
    for (int j = 0; j < 4; j++) {
        int n = x0 + ty + 8 * j;
        int k = y0 + tx;
        dst[(size_t)n * K + k] = tile[tx][ty + 8 * j];
    }
}

// -------------------------- grouped TF32 MMA GEMM ---------------------------
// Per z: C[M,N] = ep( A[M,K](lda) @ Bt[n][k]^T ). M%64==0, K%16==0.
// A must already be tf32-rounded at rest. Bt[Np][K] tf32, Np >= tile span.
struct GArgs {
    const float* A[5];
    const float* B[5];
    float*       C[5];
    const float* tm[5];
    int ep[5];
    int N[5];
    int lda[5];
    int K;
    const float* x;
    const float* xx;
    const float* bias;
};

#define TBM 64
#define TBN 128
#define TBK 16
#define A_STG 5120u            // 64 rows * 80B
#define B_STG 10240u           // 128 rows * 80B
#define STG_TOT 15360u
#define GEMM_DSMEM (4*15360)   // 61440

#define ISSUE_TILE(tile)                                                       \
    {                                                                          \
        int k0_ = (tile) * TBK;                                                \
        uint32_t st_ = smb + ((tile) & 3) * STG_TOT;                           \
        int row_ = tid >> 1;                                                   \
        int ch_  = (tid & 1);                                                  \
        const float* Ap_ = A + (size_t)(bm + row_) * lda + k0_ + ch_ * 8;      \
        cpasync16(st_ + row_ * 80 + ch_ * 32,      Ap_);                       \
        cpasync16(st_ + row_ * 80 + ch_ * 32 + 16, Ap_ + 4);                   \
        const float* Bp0_ = B + (size_t)(bn + row_) * K + k0_ + ch_ * 8;       \
        const float* Bp1_ = B + (size_t)(bn + row_ + 64) * K + k0_ + ch_ * 8;  \
        uint32_t sb_ = st_ + A_STG;                                            \
        cpasync16(sb_ + row_ * 80 + ch_ * 32,             Bp0_);               \
        cpasync16(sb_ + row_ * 80 + ch_ * 32 + 16,        Bp0_ + 4);           \
        cpasync16(sb_ + (row_ + 64) * 80 + ch_ * 32,      Bp1_);               \
        cpasync16(sb_ + (row_ + 64) * 80 + ch_ * 32 + 16, Bp1_ + 4);           \
        asm volatile("cp.async.commit_group;");                                \
    }

__global__ void __launch_bounds__(128, 3) gemm_kernel(GArgs ga)
{
    extern __shared__ float sdyn[];

    const int z = blockIdx.z;
    const float* __restrict__ A = ga.A[z];
    const float* __restrict__ B = ga.B[z];
    float* __restrict__ C = ga.C[z];
    const int N   = ga.N[z];
    const int lda = ga.lda[z];
    const int K   = ga.K;
    const int ep  = ga.ep[z];

    const int bn = blockIdx.x * TBN;
    if (bn >= N) return;
    const int bm = blockIdx.y * TBM;

    const int tid  = threadIdx.x;
    const int lane = tid & 31;
    const int wid  = tid >> 5;
    const int gr = lane >> 2, gc = lane & 3;
    const int wm = (wid & 1) * 32;
    const int wn = (wid >> 1) * 64;

    const uint32_t smb = (uint32_t)__cvta_generic_to_shared(sdyn);

    const int p  = lane >> 3;
    const int pr = lane & 7;
    const uint32_t a_lane = smb + (uint32_t)((wm + (p & 1) * 8 + pr) * 80 + (p >> 1) * 16);
    const uint32_t b_lane = smb + A_STG + (uint32_t)((wn + (p >> 1) * 8 + pr) * 80 + (p & 1) * 16);

    float acc[2][8][4];
#pragma unroll
    for (int mi = 0; mi < 2; mi++)
#pragma unroll
        for (int ni = 0; ni < 8; ni++)
#pragma unroll
            for (int c = 0; c < 4; c++) acc[mi][ni][c] = 0.f;

    const int niter = K / TBK;
    ISSUE_TILE(0)
    if (niter > 1) ISSUE_TILE(1)
    if (niter > 2) ISSUE_TILE(2)

    for (int it = 0; it < niter; it++) {
        const int remafter = niter - it - 1;
        if (remafter >= 2)      asm volatile("cp.async.wait_group 2;");
        else if (remafter == 1) asm volatile("cp.async.wait_group 1;");
        else                    asm volatile("cp.async.wait_group 0;");
        __syncthreads();

        if (it + 3 < niter) ISSUE_TILE(it + 3)

        const uint32_t abase = a_lane + (uint32_t)(it & 3) * STG_TOT;
        const uint32_t bbase = b_lane + (uint32_t)(it & 3) * STG_TOT;
#pragma unroll
        for (int kk = 0; kk < TBK; kk += 8) {
            uint32_t af[2][4], bf[4][4];
#pragma unroll
            for (int mi = 0; mi < 2; mi++)
                LDSM4(af[mi][0], af[mi][1], af[mi][2], af[mi][3],
                      abase + mi * 1280 + kk * 4)
#pragma unroll
            for (int P = 0; P < 4; P++)
                LDSM4(bf[P][0], bf[P][1], bf[P][2], bf[P][3],
                      bbase + P * 1280 + kk * 4)
#pragma unroll
            for (int mi = 0; mi < 2; mi++)
#pragma unroll
                for (int ni = 0; ni < 8; ni++)
                    mma_tf32(acc[mi][ni], af[mi],
                             bf[ni >> 1][(ni & 1) * 2],
                             bf[ni >> 1][(ni & 1) * 2 + 1]);
        }
        __syncthreads();
    }

    // ---------------- staged, coalesced epilogue ----------------
    float* Cs = sdyn;      // 64 x 132 fp32 tile (33.8KB <= 60KB)
#pragma unroll
    for (int mi = 0; mi < 2; mi++)
#pragma unroll
        for (int ni = 0; ni < 8; ni++)
#pragma unroll
            for (int cp = 0; cp < 2; cp++) {
                int row = wm + mi * 16 + gr + cp * 8;
                int col = wn + ni * 8 + 2 * gc;
                *(float2*)&Cs[row * 132 + col] =
                    make_float2(acc[mi][ni][cp * 2], acc[mi][ni][cp * 2 + 1]);
            }
    __syncthreads();

    const float* tmv = ga.tm[z];
#pragma unroll
    for (int ps = 0; ps < 16; ps++) {
        int row  = ps * 4 + wid;
        int col  = lane * 4;
        int grow = bm + row;
        int gcol = bn + col;
        if (gcol + 3 < N) {
            float4 v = *(float4*)&Cs[row * 132 + col];
            if (ep == EP_TANH) {
                v.x = f2tf32(tanhf(v.x)); v.y = f2tf32(tanhf(v.y));
                v.z = f2tf32(tanhf(v.z)); v.w = f2tf32(tanhf(v.w));
            } else if (ep == EP_SILU) {
                v.x = v.x / (1.f + expf(-v.x)); v.y = v.y / (1.f + expf(-v.y));
                v.z = v.z / (1.f + expf(-v.z)); v.w = v.w / (1.f + expf(-v.w));
            } else if (ep == EP_EXPW) {
                v.x = expf(ga.bias[gcol]     + v.x);
                v.y = expf(ga.bias[gcol + 1] + v.y);
                v.z = expf(ga.bias[gcol + 2] + v.z);
                v.w = expf(ga.bias[gcol + 3] + v.w);
            } else if (ep == EP_MIX) {
                size_t ix = (size_t)grow * CC + gcol;
                float4 x4  = *(const float4*)(ga.x + ix);
                float4 xx4 = *(const float4*)(ga.xx + ix);
                float4 t4  = *(const float4*)(tmv + gcol);
                v.x = f2tf32(fmaf(xx4.x, t4.x + v.x, x4.x));
                v.y = f2tf32(fmaf(xx4.y, t4.y + v.y, x4.y));
                v.z = f2tf32(fmaf(xx4.z, t4.z + v.z, x4.z));
                v.w = f2tf32(fmaf(xx4.w, t4.w + v.w, x4.w));
            }
            *(float4*)&C[(size_t)grow * N + gcol] = v;
        } else if (gcol < N) {
            for (int e = 0; e < 4 && gcol + e < N; e++) {
                float v0 = Cs[row * 132 + col + e];
                if (ep == EP_TANH) v0 = f2tf32(tanhf(v0));
                else if (ep == EP_SILU) v0 = v0 / (1.f + expf(-v0));
                else if (ep == EP_EXPW) v0 = expf(ga.bias[gcol + e] + v0);
                else if (ep == EP_MIX) {
                    size_t ix = (size_t)grow * CC + gcol + e;
                    v0 = f2tf32(fmaf(ga.xx[ix], tmv[gcol + e] + v0, ga.x[ix]));
                }
                C[(size_t)grow * N + gcol + e] = v0;
            }
        }
    }
}

// ------------------------- q_shift + maa_x mix (float4) ---------------------
__global__ void shift_kernel(const float* __restrict__ x,
                             const float* __restrict__ tmx,
                             float* __restrict__ xx,
                             float* __restrict__ xxx)
{
    int idx = blockIdx.x * blockDim.x + threadIdx.x;
    if (idx >= MM * (CC/4)) return;
    int c4i = idx % (CC/4);
    int m   = idx / (CC/4);
    int c   = c4i * 4;
    int b = m >> 10;
    int t = m & 1023;
    int hh = t >> 5;
    int w  = t & 31;
    int q  = c / C4;
    int sh = hh + ((q == 2) ? -1 : (q == 3) ? 1 : 0);
    int sw = w  + ((q == 0) ? -1 : (q == 1) ? 1 : 0);
    float4 xs = make_float4(0.f, 0.f, 0.f, 0.f);
    if (sh >= 0 && sh < HP_ && sw >= 0 && sw < WP_)
        xs = *(const float4*)(x + ((size_t)((b << 10) + (sh << 5) + sw)) * CC + c);
    float4 xv = ((const float4*)x)[idx];
    float4 tm = *(const float4*)(tmx + c);
    float4 d, o;
    d.x = xs.x - xv.x; d.y = xs.y - xv.y; d.z = xs.z - xv.z; d.w = xs.w - xv.w;
    o.x = f2tf32(fmaf(d.x, tm.x, xv.x)); o.y = f2tf32(fmaf(d.y, tm.y, xv.y));
    o.z = f2tf32(fmaf(d.z, tm.z, xv.z)); o.w = f2tf32(fmaf(d.w, tm.w, xv.w));
    ((float4*)xx)[idx]  = d;
    ((float4*)xxx)[idx] = o;
}

// ----------------------------- chunked WKV6 (i-split x2) --------------------
// 192 blocks: block bx -> head bx>>1, i-half bx&1 (16 output channels).
__global__ void __launch_bounds__(256) wkv_chunk_kernel(
    const float* __restrict__ r, const float* __restrict__ k,
    const float* __restrict__ v, const float* __restrict__ ew,
    const float* __restrict__ u, float* __restrict__ y)
{
    __shared__ float sr[CL][36], sk[CL][36], se[CL][36];
    __shared__ float scum[CL][36], sKtT[HSZ][36], satt[CL][36];
    __shared__ float sv[CL][20], sS[HSZ][20];
    __shared__ float sdiag[CL], scend[HSZ], su[HSZ];

    const int head = blockIdx.x >> 1;
    const int ioff = (blockIdx.x & 1) * 16;
    const int b = head / NHD, h = head % NHD;
    const int tid  = threadIdx.x;
    const int lane = tid & 31;
    const int wid  = tid >> 5;
    const int tld = tid >> 3;           // 0..31 row
    const int jld = (tid & 7) << 2;     // full-width col base (x4)
    const int il2 = (tid & 7) << 1;     // half-width col base (x2)

    if (tid < HSZ) su[tid] = u[h * HSZ + tid];
    for (int zz = tid; zz < HSZ * 20; zz += 256) ((float*)sS)[zz] = 0.f;

    const size_t base = (size_t)b * TT * CC + (size_t)h * HSZ;

    size_t g0 = base + (size_t)tld * CC + jld;
    float4 r4 = *(const float4*)(r  + g0);
    float4 k4 = *(const float4*)(k  + g0);
    float4 e4 = *(const float4*)(ew + g0);
    float2 v2 = *(const float2*)(v + base + (size_t)tld * CC + ioff + il2);
    __syncthreads();

    for (int c0 = 0; c0 < TT; c0 += CL) {
        *(float4*)&sr[tld][jld] = r4;
        *(float4*)&sk[tld][jld] = k4;
        *(float4*)&se[tld][jld] = e4;
        *(float2*)&sv[tld][il2] = v2;
        __syncthreads();

        // cumsum over t (warp scan; warp wid owns j = wid*4..+3)
#pragma unroll
        for (int q = 0; q < 4; q++) {
            int j = wid * 4 + q;
            float vv = se[lane][j];
#pragma unroll
            for (int off = 1; off < 32; off <<= 1) {
                float nb = __shfl_up_sync(0xffffffffu, vv, off);
                if (lane >= off) vv += nb;
            }
            scum[lane][j] = vv;
            if (lane == 31) scend[j] = vv;
        }
        // diag
        {
            float pp = 0.f;
#pragma unroll
            for (int e = 0; e < 4; e++)
                pp += sr[tld][jld + e] * su[jld + e] * sk[tld][jld + e];
            pp += __shfl_xor_sync(0xffffffffu, pp, 1);
            pp += __shfl_xor_sync(0xffffffffu, pp, 2);
            pp += __shfl_xor_sync(0xffffffffu, pp, 4);
            if ((lane & 7) == 0) sdiag[tld] = pp;
        }
        __syncthreads();

        // transform
#pragma unroll
        for (int e = 0; e < 4; e++) {
            int j = jld + e;
            float cum = scum[tld][j];
            float ev  = se[tld][j];
            float rw  = sr[tld][j];
            float kw  = sk[tld][j];
            sr[tld][j]   = rw * expf(ev - cum);
            sKtT[j][tld] = kw * expf(cum);
            scum[tld][j] = kw * expf(cum - scend[j]);
        }
        __syncthreads();

        // att = R~ @ Kt^T, masked (full 32x32)
        {
            const int t = tld, t4 = jld;
            float a0 = 0.f, a1 = 0.f, a2 = 0.f, a3 = 0.f;
#pragma unroll
            for (int j = 0; j < HSZ; j++) {
                float rt = sr[t][j];
                float4 kt = *(const float4*)&sKtT[j][t4];
                a0 = fmaf(rt, kt.x, a0); a1 = fmaf(rt, kt.y, a1);
                a2 = fmaf(rt, kt.z, a2); a3 = fmaf(rt, kt.w, a3);
            }
            float dv = sdiag[t];
            satt[t][t4+0] = (t4+0 < t) ? a0 : ((t4+0 == t) ? dv : 0.f);
            satt[t][t4+1] = (t4+1 < t) ? a1 : ((t4+1 == t) ? dv : 0.f);
            satt[t][t4+2] = (t4+2 < t) ? a2 : ((t4+2 == t) ? dv : 0.f);
            satt[t][t4+3] = (t4+3 < t) ? a3 : ((t4+3 == t) ? dv : 0.f);
        }
        __syncthreads();

        // prefetch next chunk
        if (c0 + CL < TT) {
            size_t gn = base + (size_t)(c0 + CL + tld) * CC + jld;
            r4 = *(const float4*)(r  + gn);
            k4 = *(const float4*)(k  + gn);
            e4 = *(const float4*)(ew + gn);
            v2 = *(const float2*)(v + base + (size_t)(c0 + CL + tld) * CC + ioff + il2);
        }

        // Y[:, ioff..+16] = att @ V + R~ @ S    (float2 per thread)
        {
            const int t = tld;
            float2 acc = make_float2(0.f, 0.f);
#pragma unroll
            for (int tau = 0; tau < CL; tau++) {
                float at = satt[t][tau];
                float2 vv = *(const float2*)&sv[tau][il2];
                acc.x = fmaf(at, vv.x, acc.x); acc.y = fmaf(at, vv.y, acc.y);
            }
#pragma unroll
            for (int j = 0; j < HSZ; j++) {
                float rt = sr[t][j];
                float2 sj = *(const float2*)&sS[j][il2];
                acc.x = fmaf(rt, sj.x, acc.x); acc.y = fmaf(rt, sj.y, acc.y);
            }
            *(float2*)(y + base + (size_t)(c0 + t) * CC + ioff + il2) = acc;
        }
        __syncthreads();

        // S = exp(-cum_end) * S + Kh^T @ V
        {
            const int j = tld;
            float dend = expf(-scend[j]);
            float2 s = *(const float2*)&sS[j][il2];
            s.x *= dend; s.y *= dend;
#pragma unroll
            for (int tau = 0; tau < CL; tau++) {
                float kh = scum[tau][j];
                float2 vv = *(const float2*)&sv[tau][il2];
                s.x = fmaf(kh, vv.x, s.x); s.y = fmaf(kh, vv.y, s.y);
            }
            *(float2*)&sS[j][il2] = s;
        }
        __syncthreads();
    }
}

// --------------------------- LayerNorm * gate -------------------------------
__global__ void __launch_bounds__(256) ln_gate_kernel(
    const float* __restrict__ y, const float* __restrict__ g,
    const float* __restrict__ lw, const float* __restrict__ lb,
    float* __restrict__ out)
{
    __shared__ float red[8];
    int m = blockIdx.x;
    int t = threadIdx.x;
    size_t base = (size_t)m * CC;
    float v0 = y[base + t], v1 = y[base + t + 256], v2 = y[base + t + 512];
    float s = v0 + v1 + v2;
#pragma unroll
    for (int o = 16; o; o >>= 1) s += __shfl_xor_sync(0xffffffffu, s, o);
    if ((t & 31) == 0) red[t >> 5] = s;
    __syncthreads();
    float tot = red[0]+red[1]+red[2]+red[3]+red[4]+red[5]+red[6]+red[7];
    float mu = tot * (1.f / CC);
    float d0 = v0 - mu, d1 = v1 - mu, d2 = v2 - mu;
    float q = d0*d0 + d1*d1 + d2*d2;
#pragma unroll
    for (int o = 16; o; o >>= 1) q += __shfl_xor_sync(0xffffffffu, q, o);
    __syncthreads();
    if ((t & 31) == 0) red[t >> 5] = q;
    __syncthreads();
    float var = (red[0]+red[1]+red[2]+red[3]+red[4]+red[5]+red[6]+red[7]) * (1.f / CC);
    float inv = rsqrtf(var + 1e-5f);
    out[base + t]       = f2tf32((d0 * inv * lw[t]       + lb[t])       * g[base + t]);
    out[base + t + 256] = f2tf32((d1 * inv * lw[t + 256] + lb[t + 256]) * g[base + t + 256]);
    out[base + t + 512] = f2tf32((d2 * inv * lw[t + 512] + lb[t + 512]) * g[base + t + 512]);
}

// ------------------------------- launcher -----------------------------------
extern "C" void kernel_launch(void* const* d_in, const int* in_sizes, int n_in,
                              void* d_out, int out_size)
{
    const float* x    = (const float*)d_in[0];
    const float* tmx  = (const float*)d_in[1];
    const float* tmw  = (const float*)d_in[2];
    const float* tmk  = (const float*)d_in[3];
    const float* tmv  = (const float*)d_in[4];
    const float* tmr  = (const float*)d_in[5];
    const float* tmg  = (const float*)d_in[6];
    const float* w1   = (const float*)d_in[7];
    const float* w2   = (const float*)d_in[8];
    const float* tdec = (const float*)d_in[9];
    const float* dw1  = (const float*)d_in[10];
    const float* dw2  = (const float*)d_in[11];
    const float* faaa = (const float*)d_in[12];
    const float* W_r  = (const float*)d_in[13];
    const float* W_k  = (const float*)d_in[14];
    const float* W_v  = (const float*)d_in[15];
    const float* W_g  = (const float*)d_in[16];
    const float* W_o  = (const float*)d_in[17];
    const float* lnw  = (const float*)d_in[18];
    const float* lnb  = (const float*)d_in[19];
    float* out = (float*)d_out;

    static int attr_set = 0;
    if (!attr_set) {
        cudaFuncSetAttribute(gemm_kernel,
                             cudaFuncAttributeMaxDynamicSharedMemorySize,
                             GEMM_DSMEM);
        attr_set = 1;
    }

    float* buf = nullptr;
    cudaGetSymbolAddress((void**)&buf, g_scratch);

    float* xx  = buf;
    float* xxx = buf + 1 * SSLOT;
    float* m0  = buf + 2 * SSLOT;
    float* m1  = buf + 3 * SSLOT;
    float* m2  = buf + 4 * SSLOT;
    float* m3  = buf + 5 * SSLOT;
    float* m4  = buf + 6 * SSLOT;
    float* rr  = buf + 7 * SSLOT;
    float* kk  = buf + 8 * SSLOT;
    float* vv  = buf + 9 * SSLOT;
    float* gg  = buf + 10 * SSLOT;
    float* eww = buf + 11 * SSLOT;
    float* yy  = buf + 12 * SSLOT;
    float* G1  = buf + 13 * SSLOT;
    float* ww  = buf + 13 * SSLOT + 1048576;
    float* ln  = xx;

    float* Wt_r = buf + 14 * SSLOT;
    float* Wt_k = Wt_r + 589824;
    float* Wt_v = Wt_k + 589824;
    float* Wt_g = Wt_v + 589824;
    float* Wt_o = Wt_g + 589824;
    float* w1t  = Wt_o + 589824;        // 256 x 768
    float* dw1t = buf + 15 * SSLOT;     // 128 x 768 (padded)
    float* dw2t = dw1t + 98304;         // 768 x 64
    float* w2t  = dw2t + 49152;         // 5 x 768 x 32

    const int EW4 = (MM * (CC/4) + 255) / 256;

    // 0) weight transposes + tf32 pre-round
    {
        TArgs ta = {};
        const float* srcs[NTR] = {W_r, W_k, W_v, W_g, W_o, w1, dw1, dw2,
                                  w2, w2 + 32*768, w2 + 2*32*768,
                                  w2 + 3*32*768, w2 + 4*32*768};
        float* dsts[NTR] = {Wt_r, Wt_k, Wt_v, Wt_g, Wt_o, w1t, dw1t, dw2t,
                            w2t, w2t + 24576, w2t + 2*24576,
                            w2t + 3*24576, w2t + 4*24576};
        int Ks[NTR]  = {768,768,768,768,768, 768, 768, 64, 32,32,32,32,32};
        int Ns[NTR]  = {768,768,768,768,768, 160,  64, 768, 768,768,768,768,768};
        int Nps[NTR] = {768,768,768,768,768, 256, 128, 768, 768,768,768,768,768};
        for (int i = 0; i < NTR; i++) {
            ta.src[i] = srcs[i]; ta.dst[i] = dsts[i];
            ta.K[i] = Ks[i]; ta.N[i] = Ns[i]; ta.Np[i] = Nps[i];
        }
        transpose_kernel<<<dim3(24, 24, NTR), dim3(32, 8)>>>(ta);
    }

    // 1) q-shift + maa_x mix
    shift_kernel<<<EW4, 256>>>(x, tmx, xx, xxx);

    // 2) G1 = tanh(xxx @ w1)
    {
        GArgs a = {};
        a.A[0] = xxx; a.B[0] = w1t; a.C[0] = G1;
        a.ep[0] = EP_TANH; a.N[0] = 160; a.lda[0] = CC; a.K = CC;
        gemm_kernel<<<dim3(2, 64, 1), 128, GEMM_DSMEM>>>(a);
    }

    // 3) 5 mix GEMMs (K=32), fused mix epilogue
    {
        GArgs a = {};
        float* mouts[5] = {m0, m1, m2, m3, m4};
        const float* tms[5] = {tmw, tmk, tmv, tmr, tmg};
        for (int q = 0; q < 5; q++) {
            a.A[q] = G1 + q * 32;
            a.B[q] = w2t + (size_t)q * 24576;
            a.C[q] = mouts[q];
            a.tm[q] = tms[q];
            a.ep[q] = EP_MIX; a.N[q] = CC; a.lda[q] = 160;
        }
        a.K = 32; a.x = x; a.xx = xx;
        gemm_kernel<<<dim3(6, 64, 5), 128, GEMM_DSMEM>>>(a);
    }

    // 4) grouped projections: r,k,v,g (N=768) + dw1 (N=64), K=768
    {
        GArgs a = {};
        a.A[0] = m3; a.B[0] = Wt_r; a.C[0] = rr; a.ep[0] = EP_NONE; a.N[0] = CC; a.lda[0] = CC;
        a.A[1] = m1; a.B[1] = Wt_k; a.C[1] = kk; a.ep[1] = EP_NONE; a.N[1] = CC; a.lda[1] = CC;
        a.A[2] = m2; a.B[2] = Wt_v; a.C[2] = vv; a.ep[2] = EP_NONE; a.N[2] = CC; a.lda[2] = CC;
        a.A[3] = m4; a.B[3] = Wt_g; a.C[3] = gg; a.ep[3] = EP_SILU; a.N[3] = CC; a.lda[3] = CC;
        a.A[4] = m0; a.B[4] = dw1t; a.C[4] = ww; a.ep[4] = EP_TANH; a.N[4] = 64; a.lda[4] = CC;
        a.K = CC;
        gemm_kernel<<<dim3(6, 64, 5), 128, GEMM_DSMEM>>>(a);
    }

    // 5) eww = exp(tdec + ww @ dw2)
    {
        GArgs a = {};
        a.A[0] = ww; a.B[0] = dw2t; a.C[0] = eww;
        a.ep[0] = EP_EXPW; a.N[0] = CC; a.lda[0] = 64; a.K = 64;
        a.bias = tdec;
        gemm_kernel<<<dim3(6, 64, 1), 128, GEMM_DSMEM>>>(a);
    }

    // 6) chunked WKV6 (i-split x2)
    wkv_chunk_kernel<<<BBATCH * NHD * 2, 256>>>(rr, kk, vv, eww, faaa, yy);

    // 7) LayerNorm * gate
    ln_gate_kernel<<<MM, 256>>>(yy, gg, lnw, lnb, ln);

    // 8) output projection
    {
        GArgs a = {};
        a.A[0] = ln; a.B[0] = Wt_o; a.C[0] = out;
        a.ep[0] = EP_NONE; a.N[0] = CC; a.lda[0] = CC; a.K = CC;
        gemm_kernel<<<dim3(6, 64, 1), 128, GEMM_DSMEM>>>(a);
    }

    (void)in_sizes; (void)n_in; (void)out_size;
}

// round 8
// speedup vs baseline: 1.0792x; 1.0792x over previous
#include <cuda_runtime.h>
#include <math.h>
#include <stdint.h>

// ----------------------------- problem constants ---------------------------
#define CC   768
#define TT   1024
#define BBATCH 4
#define MM   (BBATCH*TT)
#define NHD  24
#define HSZ  32
#define HP_  32
#define WP_  32
#define C4   (CC/4)
#define CL   32

#define SSLOT 3145728ull
__device__ float g_scratch[16ull*SSLOT];

enum { EP_NONE = 0, EP_TANH = 1, EP_SILU = 2, EP_EXPW = 3, EP_MIX = 4 };

// ----------------------------- TF32 helpers --------------------------------
__device__ __forceinline__ float f2tf32(float x) {
    uint32_t r;
    asm("cvt.rna.tf32.f32 %0, %1;" : "=r"(r) : "f"(x));
    return __uint_as_float(r);
}

__device__ __forceinline__ void mma_tf32(float acc[4], const uint32_t a[4],
                                         const uint32_t b0, const uint32_t b1) {
    asm volatile(
        "mma.sync.aligned.m16n8k8.row.col.f32.tf32.tf32.f32 "
        "{%0,%1,%2,%3}, {%4,%5,%6,%7}, {%8,%9}, {%0,%1,%2,%3};"
        : "+f"(acc[0]), "+f"(acc[1]), "+f"(acc[2]), "+f"(acc[3])
        : "r"(a[0]), "r"(a[1]), "r"(a[2]), "r"(a[3]), "r"(b0), "r"(b1));
}

#define LDSM4(d0, d1, d2, d3, addr)                                           \
    asm volatile("ldmatrix.sync.aligned.m8n8.x4.shared.b16 {%0,%1,%2,%3}, [%4];" \
                 : "=r"(d0), "=r"(d1), "=r"(d2), "=r"(d3) : "r"(addr));

__device__ __forceinline__ void cpasync16(uint32_t saddr, const void* gptr) {
    asm volatile("cp.async.cg.shared.global [%0], [%1], 16;"
                 :: "r"(saddr), "l"(gptr));
}

// --------------------- weight transpose + tf32 pre-round --------------------
#define NTR 13
struct TArgs {
    const float* src[NTR];
    float*       dst[NTR];
    int K[NTR];
    int N[NTR];
    int Np[NTR];
};

__global__ void transpose_kernel(TArgs ta)
{
    __shared__ float tile[32][33];
    const int z = blockIdx.z;
    const int K = ta.K[z], N = ta.N[z], Np = ta.Np[z];
    const int x0 = blockIdx.x * 32;
    const int y0 = blockIdx.y * 32;
    if (x0 >= Np || y0 >= K) return;
    const float* src = ta.src[z];
    float* dst = ta.dst[z];
    const int tx = threadIdx.x, ty = threadIdx.y;
#pragma unroll
    for (int j = 0; j < 4; j++) {
        int k = y0 + ty + 8 * j;
        int n = x0 + tx;
        float v = (n < N) ? src[(size_t)k * N + n] : 0.f;
        tile[ty + 8 * j][tx] = f2tf32(v);
    }
    __syncthreads();
#pragma unroll
    for (int j = 0; j < 4; j++) {
        int n = x0 + ty + 8 * j;
        int k = y0 + tx;
        dst[(size_t)n * K + k] = tile[tx][ty + 8 * j];
    }
}

// -------------------------- grouped TF32 MMA GEMM ---------------------------
// Per z: C[M,N] = ep( A[M,K](lda) @ Bt[n][k]^T ). M%128==0, K%16==0.
// A must already be tf32-rounded at rest. Bt[Np][K] tf32, Np >= tile span.
struct GArgs {
    const float* A[5];
    const float* B[5];
    float*       C[5];
    const float* tm[5];
    int ep[5];
    int N[5];
    int lda[5];
    int K;
    const float* x;
    const float* xx;
    const float* bias;
};

#define TBM 128
#define TBN 128
#define TBK 16
#define STAGE_B 10240u
#define GEMM_DSMEM 81920

#define ISSUE_TILE(tile)                                                       \
    {                                                                          \
        int k0_ = (tile) * TBK;                                                \
        uint32_t sa_ = as_u + ((tile) & 3) * STAGE_B;                          \
        uint32_t sb_ = bs_u + ((tile) & 3) * STAGE_B;                          \
        int row_ = tid >> 2;                                                   \
        int chb_ = (tid & 3) * 16;                                             \
        int chf_ = (tid & 3) * 4;                                              \
        cpasync16(sa_ + row_ * 80 + chb_,                                      \
                  A + (size_t)(bm + row_) * lda + k0_ + chf_);                 \
        cpasync16(sa_ + (row_ + 64) * 80 + chb_,                               \
                  A + (size_t)(bm + row_ + 64) * lda + k0_ + chf_);            \
        cpasync16(sb_ + row_ * 80 + chb_,                                      \
                  B + (size_t)(bn + row_) * K + k0_ + chf_);                   \
        cpasync16(sb_ + (row_ + 64) * 80 + chb_,                               \
                  B + (size_t)(bn + row_ + 64) * K + k0_ + chf_);              \
        asm volatile("cp.async.commit_group;");                                \
    }

__global__ void __launch_bounds__(256, 2) gemm_kernel(GArgs ga)
{
    extern __shared__ float sdyn[];

    const int z = blockIdx.z;
    const float* __restrict__ A = ga.A[z];
    const float* __restrict__ B = ga.B[z];
    float* __restrict__ C = ga.C[z];
    const int N   = ga.N[z];
    const int lda = ga.lda[z];
    const int K   = ga.K;
    const int ep  = ga.ep[z];

    const int bn = blockIdx.x * TBN;
    if (bn >= N) return;
    const int bm = blockIdx.y * TBM;

    const int tid  = threadIdx.x;
    const int lane = tid & 31;
    const int wid  = tid >> 5;
    const int gr = lane >> 2, gc = lane & 3;
    const int wm = (wid & 3) * 32;
    const int wn = (wid >> 2) * 64;

    const uint32_t as_u = (uint32_t)__cvta_generic_to_shared(sdyn);
    const uint32_t bs_u = as_u + 4 * STAGE_B;

    const int p  = lane >> 3;
    const int pr = lane & 7;
    const uint32_t a_lane = as_u + (uint32_t)((wm + (p & 1) * 8 + pr) * 80 + (p >> 1) * 16);
    const uint32_t b_lane = bs_u + (uint32_t)((wn + (p >> 1) * 8 + pr) * 80 + (p & 1) * 16);

    float acc[2][8][4];
#pragma unroll
    for (int mi = 0; mi < 2; mi++)
#pragma unroll
        for (int ni = 0; ni < 8; ni++)
#pragma unroll
            for (int c = 0; c < 4; c++) acc[mi][ni][c] = 0.f;

    const int niter = K / TBK;
    ISSUE_TILE(0)
    if (niter > 1) ISSUE_TILE(1)
    if (niter > 2) ISSUE_TILE(2)

    for (int it = 0; it < niter; it++) {
        const int remafter = niter - it - 1;
        if (remafter >= 2)      asm volatile("cp.async.wait_group 2;");
        else if (remafter == 1) asm volatile("cp.async.wait_group 1;");
        else                    asm volatile("cp.async.wait_group 0;");
        __syncthreads();

        if (it + 3 < niter) ISSUE_TILE(it + 3)

        const uint32_t abase = a_lane + (uint32_t)(it & 3) * STAGE_B;
        const uint32_t bbase = b_lane + (uint32_t)(it & 3) * STAGE_B;
#pragma unroll
        for (int kk = 0; kk < TBK; kk += 8) {
            uint32_t af[2][4], bf[4][4];
#pragma unroll
            for (int mi = 0; mi < 2; mi++)
                LDSM4(af[mi][0], af[mi][1], af[mi][2], af[mi][3],
                      abase + mi * 1280 + kk * 4)
#pragma unroll
            for (int P = 0; P < 4; P++)
                LDSM4(bf[P][0], bf[P][1], bf[P][2], bf[P][3],
                      bbase + P * 1280 + kk * 4)
#pragma unroll
            for (int mi = 0; mi < 2; mi++)
#pragma unroll
                for (int ni = 0; ni < 8; ni++)
                    mma_tf32(acc[mi][ni], af[mi],
                             bf[ni >> 1][(ni & 1) * 2],
                             bf[ni >> 1][(ni & 1) * 2 + 1]);
        }
        __syncthreads();
    }

    // ---------------- staged, coalesced epilogue ----------------
    float* Cs = sdyn;
#pragma unroll
    for (int mi = 0; mi < 2; mi++)
#pragma unroll
        for (int ni = 0; ni < 8; ni++)
#pragma unroll
            for (int cp = 0; cp < 2; cp++) {
                int row = wm + mi * 16 + gr + cp * 8;
                int col = wn + ni * 8 + 2 * gc;
                *(float2*)&Cs[row * 132 + col] =
                    make_float2(acc[mi][ni][cp * 2], acc[mi][ni][cp * 2 + 1]);
            }
    __syncthreads();

    const float* tmv = ga.tm[z];
#pragma unroll
    for (int ps = 0; ps < 16; ps++) {
        int row  = ps * 8 + wid;
        int col  = lane * 4;
        int grow = bm + row;
        int gcol = bn + col;
        if (gcol + 3 < N) {
            float4 v = *(float4*)&Cs[row * 132 + col];
            if (ep == EP_TANH) {
                v.x = f2tf32(tanhf(v.x)); v.y = f2tf32(tanhf(v.y));
                v.z = f2tf32(tanhf(v.z)); v.w = f2tf32(tanhf(v.w));
            } else if (ep == EP_SILU) {
                v.x = v.x / (1.f + expf(-v.x)); v.y = v.y / (1.f + expf(-v.y));
                v.z = v.z / (1.f + expf(-v.z)); v.w = v.w / (1.f + expf(-v.w));
            } else if (ep == EP_EXPW) {
                v.x = expf(ga.bias[gcol]     + v.x);
                v.y = expf(ga.bias[gcol + 1] + v.y);
                v.z = expf(ga.bias[gcol + 2] + v.z);
                v.w = expf(ga.bias[gcol + 3] + v.w);
            } else if (ep == EP_MIX) {
                size_t ix = (size_t)grow * CC + gcol;
                float4 x4  = *(const float4*)(ga.x + ix);
                float4 xx4 = *(const float4*)(ga.xx + ix);
                float4 t4  = *(const float4*)(tmv + gcol);
                v.x = f2tf32(fmaf(xx4.x, t4.x + v.x, x4.x));
                v.y = f2tf32(fmaf(xx4.y, t4.y + v.y, x4.y));
                v.z = f2tf32(fmaf(xx4.z, t4.z + v.z, x4.z));
                v.w = f2tf32(fmaf(xx4.w, t4.w + v.w, x4.w));
            }
            *(float4*)&C[(size_t)grow * N + gcol] = v;
        } else if (gcol < N) {
            for (int e = 0; e < 4 && gcol + e < N; e++) {
                float v0 = Cs[row * 132 + col + e];
                if (ep == EP_TANH) v0 = f2tf32(tanhf(v0));
                else if (ep == EP_SILU) v0 = v0 / (1.f + expf(-v0));
                else if (ep == EP_EXPW) v0 = expf(ga.bias[gcol + e] + v0);
                else if (ep == EP_MIX) {
                    size_t ix = (size_t)grow * CC + gcol + e;
                    v0 = f2tf32(fmaf(ga.xx[ix], tmv[gcol + e] + v0, ga.x[ix]));
                }
                C[(size_t)grow * N + gcol + e] = v0;
            }
        }
    }
}

// ------------------------- q_shift + maa_x mix (float4) ---------------------
__global__ void shift_kernel(const float* __restrict__ x,
                             const float* __restrict__ tmx,
                             float* __restrict__ xx,
                             float* __restrict__ xxx)
{
    int idx = blockIdx.x * blockDim.x + threadIdx.x;
    if (idx >= MM * (CC/4)) return;
    int c4i = idx % (CC/4);
    int m   = idx / (CC/4);
    int c   = c4i * 4;
    int b = m >> 10;
    int t = m & 1023;
    int hh = t >> 5;
    int w  = t & 31;
    int q  = c / C4;
    int sh = hh + ((q == 2) ? -1 : (q == 3) ? 1 : 0);
    int sw = w  + ((q == 0) ? -1 : (q == 1) ? 1 : 0);
    float4 xs = make_float4(0.f, 0.f, 0.f, 0.f);
    if (sh >= 0 && sh < HP_ && sw >= 0 && sw < WP_)
        xs = *(const float4*)(x + ((size_t)((b << 10) + (sh << 5) + sw)) * CC + c);
    float4 xv = ((const float4*)x)[idx];
    float4 tm = *(const float4*)(tmx + c);
    float4 d, o;
    d.x = xs.x - xv.x; d.y = xs.y - xv.y; d.z = xs.z - xv.z; d.w = xs.w - xv.w;
    o.x = f2tf32(fmaf(d.x, tm.x, xv.x)); o.y = f2tf32(fmaf(d.y, tm.y, xv.y));
    o.z = f2tf32(fmaf(d.z, tm.z, xv.z)); o.w = f2tf32(fmaf(d.w, tm.w, xv.w));
    ((float4*)xx)[idx]  = d;
    ((float4*)xxx)[idx] = o;
}

// ----------------------------- chunked WKV6 (i-split x2) --------------------
__global__ void __launch_bounds__(256) wkv_chunk_kernel(
    const float* __restrict__ r, const float* __restrict__ k,
    const float* __restrict__ v, const float* __restrict__ ew,
    const float* __restrict__ u, float* __restrict__ y)
{
    __shared__ float sr[CL][36], sk[CL][36], se[CL][36];
    __shared__ float scum[CL][36], sKtT[HSZ][36], satt[CL][36];
    __shared__ float sv[CL][20], sS[HSZ][20];
    __shared__ float sdiag[CL], scend[HSZ], su[HSZ];

    const int head = blockIdx.x >> 1;
    const int ioff = (blockIdx.x & 1) * 16;
    const int b = head / NHD, h = head % NHD;
    const int tid  = threadIdx.x;
    const int lane = tid & 31;
    const int wid  = tid >> 5;
    const int tld = tid >> 3;
    const int jld = (tid & 7) << 2;
    const int il2 = (tid & 7) << 1;

    if (tid < HSZ) su[tid] = u[h * HSZ + tid];
    for (int zz = tid; zz < HSZ * 20; zz += 256) ((float*)sS)[zz] = 0.f;

    const size_t base = (size_t)b * TT * CC + (size_t)h * HSZ;

    size_t g0 = base + (size_t)tld * CC + jld;
    float4 r4 = *(const float4*)(r  + g0);
    float4 k4 = *(const float4*)(k  + g0);
    float4 e4 = *(const float4*)(ew + g0);
    float2 v2 = *(const float2*)(v + base + (size_t)tld * CC + ioff + il2);
    __syncthreads();

    for (int c0 = 0; c0 < TT; c0 += CL) {
        *(float4*)&sr[tld][jld] = r4;
        *(float4*)&sk[tld][jld] = k4;
        *(float4*)&se[tld][jld] = e4;
        *(float2*)&sv[tld][il2] = v2;
        __syncthreads();

#pragma unroll
        for (int q = 0; q < 4; q++) {
            int j = wid * 4 + q;
            float vv = se[lane][j];
#pragma unroll
            for (int off = 1; off < 32; off <<= 1) {
                float nb = __shfl_up_sync(0xffffffffu, vv, off);
                if (lane >= off) vv += nb;
            }
            scum[lane][j] = vv;
            if (lane == 31) scend[j] = vv;
        }
        {
            float pp = 0.f;
#pragma unroll
            for (int e = 0; e < 4; e++)
                pp += sr[tld][jld + e] * su[jld + e] * sk[tld][jld + e];
            pp += __shfl_xor_sync(0xffffffffu, pp, 1);
            pp += __shfl_xor_sync(0xffffffffu, pp, 2);
            pp += __shfl_xor_sync(0xffffffffu, pp, 4);
            if ((lane & 7) == 0) sdiag[tld] = pp;
        }
        __syncthreads();

#pragma unroll
        for (int e = 0; e < 4; e++) {
            int j = jld + e;
            float cum = scum[tld][j];
            float ev  = se[tld][j];
            float rw  = sr[tld][j];
            float kw  = sk[tld][j];
            sr[tld][j]   = rw * expf(ev - cum);
            sKtT[j][tld] = kw * expf(cum);
            scum[tld][j] = kw * expf(cum - scend[j]);
        }
        __syncthreads();

        {
            const int t = tld, t4 = jld;
            float a0 = 0.f, a1 = 0.f, a2 = 0.f, a3 = 0.f;
#pragma unroll
            for (int j = 0; j < HSZ; j++) {
                float rt = sr[t][j];
                float4 kt = *(const float4*)&sKtT[j][t4];
                a0 = fmaf(rt, kt.x, a0); a1 = fmaf(rt, kt.y, a1);
                a2 = fmaf(rt, kt.z, a2); a3 = fmaf(rt, kt.w, a3);
            }
            float dv = sdiag[t];
            satt[t][t4+0] = (t4+0 < t) ? a0 : ((t4+0 == t) ? dv : 0.f);
            satt[t][t4+1] = (t4+1 < t) ? a1 : ((t4+1 == t) ? dv : 0.f);
            satt[t][t4+2] = (t4+2 < t) ? a2 : ((t4+2 == t) ? dv : 0.f);
            satt[t][t4+3] = (t4+3 < t) ? a3 : ((t4+3 == t) ? dv : 0.f);
        }
        __syncthreads();

        if (c0 + CL < TT) {
            size_t gn = base + (size_t)(c0 + CL + tld) * CC + jld;
            r4 = *(const float4*)(r  + gn);
            k4 = *(const float4*)(k  + gn);
            e4 = *(const float4*)(ew + gn);
            v2 = *(const float2*)(v + base + (size_t)(c0 + CL + tld) * CC + ioff + il2);
        }

        {
            const int t = tld;
            float2 acc = make_float2(0.f, 0.f);
#pragma unroll
            for (int tau = 0; tau < CL; tau++) {
                float at = satt[t][tau];
                float2 vv = *(const float2*)&sv[tau][il2];
                acc.x = fmaf(at, vv.x, acc.x); acc.y = fmaf(at, vv.y, acc.y);
            }
#pragma unroll
            for (int j = 0; j < HSZ; j++) {
                float rt = sr[t][j];
                float2 sj = *(const float2*)&sS[j][il2];
                acc.x = fmaf(rt, sj.x, acc.x); acc.y = fmaf(rt, sj.y, acc.y);
            }
            *(float2*)(y + base + (size_t)(c0 + t) * CC + ioff + il2) = acc;
        }
        __syncthreads();

        {
            const int j = tld;
            float dend = expf(-scend[j]);
            float2 s = *(const float2*)&sS[j][il2];
            s.x *= dend; s.y *= dend;
#pragma unroll
            for (int tau = 0; tau < CL; tau++) {
                float kh = scum[tau][j];
                float2 vv = *(const float2*)&sv[tau][il2];
                s.x = fmaf(kh, vv.x, s.x); s.y = fmaf(kh, vv.y, s.y);
            }
            *(float2*)&sS[j][il2] = s;
        }
        __syncthreads();
    }
}

// --------------------------- LayerNorm * gate -------------------------------
__global__ void __launch_bounds__(256) ln_gate_kernel(
    const float* __restrict__ y, const float* __restrict__ g,
    const float* __restrict__ lw, const float* __restrict__ lb,
    float* __restrict__ out)
{
    __shared__ float red[8];
    int m = blockIdx.x;
    int t = threadIdx.x;
    size_t base = (size_t)m * CC;
    float v0 = y[base + t], v1 = y[base + t + 256], v2 = y[base + t + 512];
    float s = v0 + v1 + v2;
#pragma unroll
    for (int o = 16; o; o >>= 1) s += __shfl_xor_sync(0xffffffffu, s, o);
    if ((t & 31) == 0) red[t >> 5] = s;
    __syncthreads();
    float tot = red[0]+red[1]+red[2]+red[3]+red[4]+red[5]+red[6]+red[7];
    float mu = tot * (1.f / CC);
    float d0 = v0 - mu, d1 = v1 - mu, d2 = v2 - mu;
    float q = d0*d0 + d1*d1 + d2*d2;
#pragma unroll
    for (int o = 16; o; o >>= 1) q += __shfl_xor_sync(0xffffffffu, q, o);
    __syncthreads();
    if ((t & 31) == 0) red[t >> 5] = q;
    __syncthreads();
    float var = (red[0]+red[1]+red[2]+red[3]+red[4]+red[5]+red[6]+red[7]) * (1.f / CC);
    float inv = rsqrtf(var + 1e-5f);
    out[base + t]       = f2tf32((d0 * inv * lw[t]       + lb[t])       * g[base + t]);
    out[base + t + 256] = f2tf32((d1 * inv * lw[t + 256] + lb[t + 256]) * g[base + t + 256]);
    out[base + t + 512] = f2tf32((d2 * inv * lw[t + 512] + lb[t + 512]) * g[base + t + 512]);
}

// ------------------------------- launcher -----------------------------------
extern "C" void kernel_launch(void* const* d_in, const int* in_sizes, int n_in,
                              void* d_out, int out_size)
{
    const float* x    = (const float*)d_in[0];
    const float* tmx  = (const float*)d_in[1];
    const float* tmw  = (const float*)d_in[2];
    const float* tmk  = (const float*)d_in[3];
    const float* tmv  = (const float*)d_in[4];
    const float* tmr  = (const float*)d_in[5];
    const float* tmg  = (const float*)d_in[6];
    const float* w1   = (const float*)d_in[7];
    const float* w2   = (const float*)d_in[8];
    const float* tdec = (const float*)d_in[9];
    const float* dw1  = (const float*)d_in[10];
    const float* dw2  = (const float*)d_in[11];
    const float* faaa = (const float*)d_in[12];
    const float* W_r  = (const float*)d_in[13];
    const float* W_k  = (const float*)d_in[14];
    const float* W_v  = (const float*)d_in[15];
    const float* W_g  = (const float*)d_in[16];
    const float* W_o  = (const float*)d_in[17];
    const float* lnw  = (const float*)d_in[18];
    const float* lnb  = (const float*)d_in[19];
    float* out = (float*)d_out;

    static int attr_set = 0;
    if (!attr_set) {
        cudaFuncSetAttribute(gemm_kernel,
                             cudaFuncAttributeMaxDynamicSharedMemorySize,
                             GEMM_DSMEM);
        attr_set = 1;
    }

    float* buf = nullptr;
    cudaGetSymbolAddress((void**)&buf, g_scratch);

    float* xx  = buf;
    float* xxx = buf + 1 * SSLOT;
    float* m0  = buf + 2 * SSLOT;
    float* m1  = buf + 3 * SSLOT;
    float* m2  = buf + 4 * SSLOT;
    float* m3  = buf + 5 * SSLOT;
    float* m4  = buf + 6 * SSLOT;
    float* rr  = buf + 7 * SSLOT;
    float* kk  = buf + 8 * SSLOT;
    float* vv  = buf + 9 * SSLOT;
    float* gg  = buf + 10 * SSLOT;
    float* eww = buf + 11 * SSLOT;
    float* yy  = buf + 12 * SSLOT;
    float* G1  = buf + 13 * SSLOT;
    float* ww  = buf + 13 * SSLOT + 1048576;
    float* ln  = xx;

    float* Wt_r = buf + 14 * SSLOT;
    float* Wt_k = Wt_r + 589824;
    float* Wt_v = Wt_k + 589824;
    float* Wt_g = Wt_v + 589824;
    float* Wt_o = Wt_g + 589824;
    float* w1t  = Wt_o + 589824;        // 256 x 768
    float* dw1t = buf + 15 * SSLOT;     // 128 x 768 (padded)
    float* dw2t = dw1t + 98304;         // 768 x 64
    float* w2t  = dw2t + 49152;         // 5 x 768 x 32

    const int EW4 = (MM * (CC/4) + 255) / 256;

    // 0) weight transposes + tf32 pre-round
    {
        TArgs ta = {};
        const float* srcs[NTR] = {W_r, W_k, W_v, W_g, W_o, w1, dw1, dw2,
                                  w2, w2 + 32*768, w2 + 2*32*768,
                                  w2 + 3*32*768, w2 + 4*32*768};
        float* dsts[NTR] = {Wt_r, Wt_k, Wt_v, Wt_g, Wt_o, w1t, dw1t, dw2t,
                            w2t, w2t + 24576, w2t + 2*24576,
                            w2t + 3*24576, w2t + 4*24576};
        int Ks[NTR]  = {768,768,768,768,768, 768, 768, 64, 32,32,32,32,32};
        int Ns[NTR]  = {768,768,768,768,768, 160,  64, 768, 768,768,768,768,768};
        int Nps[NTR] = {768,768,768,768,768, 256, 128, 768, 768,768,768,768,768};
        for (int i = 0; i < NTR; i++) {
            ta.src[i] = srcs[i]; ta.dst[i] = dsts[i];
            ta.K[i] = Ks[i]; ta.N[i] = Ns[i]; ta.Np[i] = Nps[i];
        }
        transpose_kernel<<<dim3(24, 24, NTR), dim3(32, 8)>>>(ta);
    }

    // 1) q-shift + maa_x mix
    shift_kernel<<<EW4, 256>>>(x, tmx, xx, xxx);

    // 2) G1 = tanh(xxx @ w1)
    {
        GArgs a = {};
        a.A[0] = xxx; a.B[0] = w1t; a.C[0] = G1;
        a.ep[0] = EP_TANH; a.N[0] = 160; a.lda[0] = CC; a.K = CC;
        gemm_kernel<<<dim3(2, 32, 1), 256, GEMM_DSMEM>>>(a);
    }

    // 3) 5 mix GEMMs (K=32), fused mix epilogue
    {
        GArgs a = {};
        float* mouts[5] = {m0, m1, m2, m3, m4};
        const float* tms[5] = {tmw, tmk, tmv, tmr, tmg};
        for (int q = 0; q < 5; q++) {
            a.A[q] = G1 + q * 32;
            a.B[q] = w2t + (size_t)q * 24576;
            a.C[q] = mouts[q];
            a.tm[q] = tms[q];
            a.ep[q] = EP_MIX; a.N[q] = CC; a.lda[q] = 160;
        }
        a.K = 32; a.x = x; a.xx = xx;
        gemm_kernel<<<dim3(6, 32, 5), 256, GEMM_DSMEM>>>(a);
    }

    // 4) grouped projections: r,k,v,g (N=768) + dw1 (N=64), K=768
    {
        GArgs a = {};
        a.A[0] = m3; a.B[0] = Wt_r; a.C[0] = rr; a.ep[0] = EP_NONE; a.N[0] = CC; a.lda[0] = CC;
        a.A[1] = m1; a.B[1] = Wt_k; a.C[1] = kk; a.ep[1] = EP_NONE; a.N[1] = CC; a.lda[1] = CC;
        a.A[2] = m2; a.B[2] = Wt_v; a.C[2] = vv; a.ep[2] = EP_NONE; a.N[2] = CC; a.lda[2] = CC;
        a.A[3] = m4; a.B[3] = Wt_g; a.C[3] = gg; a.ep[3] = EP_SILU; a.N[3] = CC; a.lda[3] = CC;
        a.A[4] = m0; a.B[4] = dw1t; a.C[4] = ww; a.ep[4] = EP_TANH; a.N[4] = 64; a.lda[4] = CC;
        a.K = CC;
        gemm_kernel<<<dim3(6, 32, 5), 256, GEMM_DSMEM>>>(a);
    }

    // 5) eww = exp(tdec + ww @ dw2)
    {
        GArgs a = {};
        a.A[0] = ww; a.B[0] = dw2t; a.C[0] = eww;
        a.ep[0] = EP_EXPW; a.N[0] = CC; a.lda[0] = 64; a.K = 64;
        a.bias = tdec;
        gemm_kernel<<<dim3(6, 32, 1), 256, GEMM_DSMEM>>>(a);
    }

    // 6) chunked WKV6 (i-split x2)
    wkv_chunk_kernel<<<BBATCH * NHD * 2, 256>>>(rr, kk, vv, eww, faaa, yy);

    // 7) LayerNorm * gate
    ln_gate_kernel<<<MM, 256>>>(yy, gg, lnw, lnb, ln);

    // 8) output projection
    {
        GArgs a = {};
        a.A[0] = ln; a.B[0] = Wt_o; a.C[0] = out;
        a.ep[0] = EP_NONE; a.N[0] = CC; a.lda[0] = CC; a.K = CC;
        gemm_kernel<<<dim3(6, 32, 1), 256, GEMM_DSMEM>>>(a);
    }

    (void)in_sizes; (void)n_in; (void)out_size;
}

// round 9
// speedup vs baseline: 1.4998x; 1.3898x over previous
#include <cuda_runtime.h>
#include <cuda_fp16.h>
#include <math.h>
#include <stdint.h>

// ----------------------------- problem constants ---------------------------
#define CC   768
#define TT   1024
#define BBATCH 4
#define MM   (BBATCH*TT)
#define NHD  24
#define HSZ  32
#define HP_  32
#define WP_  32
#define C4   (CC/4)
#define CL   32

#define SSLOT 3145728ull
__device__ float g_scratch[16ull*SSLOT];

enum { EP_NONE = 0, EP_TANH = 1, EP_SILU = 2, EP_EXPW = 3, EP_MIX = 4 };

// ----------------------------- MMA helpers ---------------------------------
__device__ __forceinline__ void mma_f16(float acc[4], const uint32_t a[4],
                                        const uint32_t b0, const uint32_t b1) {
    asm volatile(
        "mma.sync.aligned.m16n8k16.row.col.f32.f16.f16.f32 "
        "{%0,%1,%2,%3}, {%4,%5,%6,%7}, {%8,%9}, {%0,%1,%2,%3};"
        : "+f"(acc[0]), "+f"(acc[1]), "+f"(acc[2]), "+f"(acc[3])
        : "r"(a[0]), "r"(a[1]), "r"(a[2]), "r"(a[3]), "r"(b0), "r"(b1));
}

#define LDSM4(d0, d1, d2, d3, addr)                                           \
    asm volatile("ldmatrix.sync.aligned.m8n8.x4.shared.b16 {%0,%1,%2,%3}, [%4];" \
                 : "=r"(d0), "=r"(d1), "=r"(d2), "=r"(d3) : "r"(addr));

__device__ __forceinline__ void cpasync16(uint32_t saddr, const void* gptr) {
    asm volatile("cp.async.cg.shared.global [%0], [%1], 16;"
                 :: "r"(saddr), "l"(gptr));
}

// --------------------- weight transpose + fp16 convert ----------------------
// dst[Np][K] = half( src[K][N] )^T, zero-padded rows for n >= N.
#define NTR 13
struct TArgs {
    const float* src[NTR];
    __half*      dst[NTR];
    int K[NTR];
    int N[NTR];
    int Np[NTR];
};

__global__ void transpose_kernel(TArgs ta)
{
    __shared__ float tile[32][33];
    const int z = blockIdx.z;
    const int K = ta.K[z], N = ta.N[z], Np = ta.Np[z];
    const int x0 = blockIdx.x * 32;
    const int y0 = blockIdx.y * 32;
    if (x0 >= Np || y0 >= K) return;
    const float* src = ta.src[z];
    __half* dst = ta.dst[z];
    const int tx = threadIdx.x, ty = threadIdx.y;
#pragma unroll
    for (int j = 0; j < 4; j++) {
        int k = y0 + ty + 8 * j;
        int n = x0 + tx;
        tile[ty + 8 * j][tx] = (n < N) ? src[(size_t)k * N + n] : 0.f;
    }
    __syncthreads();
#pragma unroll
    for (int j = 0; j < 4; j++) {
        int n = x0 + ty + 8 * j;
        int k = y0 + tx;
        dst[(size_t)n * K + k] = __float2half_rn(tile[tx][ty + 8 * j]);
    }
}

// -------------------------- grouped FP16 MMA GEMM ---------------------------
// Per z: C[M,N] = ep( A[M,K](lda) @ Bt[n][k]^T ).  A, Bt fp16; acc fp32.
// M%128==0, K%32==0 (lda in elements). Bt[Np][K], Np >= tile span.
struct GArgs {
    const __half* A[5];
    const __half* B[5];
    void*         C[5];
    const float*  tm[5];
    int ep[5];
    int ch[5];       // 1 = C is half
    int N[5];
    int lda[5];
    int K;
    const float* x;
    const float* xx;
    const float* bias;
};

#define TBM 128
#define TBN 128
#define TBK 32
#define OP_B   10240u          // 128 rows * 80B per operand
#define STG_B  20480u          // A + B per stage
#define GEMM_DSMEM 81920       // 4 stages

#define ISSUE_TILE(tile)                                                       \
    {                                                                          \
        int k0_ = (tile) * TBK;                                                \
        uint32_t sa_ = smb + ((tile) & 3) * STG_B;                             \
        uint32_t sb_ = sa_ + OP_B;                                             \
        int row_ = tid >> 1;                                                   \
        int te_  = (tid & 1) * 16;                                             \
        const __half* Ap_ = A + (size_t)(bm + row_) * lda + k0_ + te_;         \
        cpasync16(sa_ + row_ * 80 + te_ * 2,      Ap_);                        \
        cpasync16(sa_ + row_ * 80 + te_ * 2 + 16, Ap_ + 8);                    \
        const __half* Bp_ = B + (size_t)(bn + row_) * K + k0_ + te_;           \
        cpasync16(sb_ + row_ * 80 + te_ * 2,      Bp_);                        \
        cpasync16(sb_ + row_ * 80 + te_ * 2 + 16, Bp_ + 8);                    \
        asm volatile("cp.async.commit_group;");                                \
    }

__global__ void __launch_bounds__(256, 2) gemm_kernel(GArgs ga)
{
    extern __shared__ float sdyn[];

    const int z = blockIdx.z;
    const __half* __restrict__ A = ga.A[z];
    const __half* __restrict__ B = ga.B[z];
    const int N   = ga.N[z];
    const int lda = ga.lda[z];
    const int K   = ga.K;
    const int ep  = ga.ep[z];
    const int chf = ga.ch[z];

    const int bn = blockIdx.x * TBN;
    if (bn >= N) return;
    const int bm = blockIdx.y * TBM;

    const int tid  = threadIdx.x;
    const int lane = tid & 31;
    const int wid  = tid >> 5;
    const int gr = lane >> 2, gc = lane & 3;
    const int wm = (wid & 3) * 32;
    const int wn = (wid >> 2) * 64;

    const uint32_t smb = (uint32_t)__cvta_generic_to_shared(sdyn);

    const int p  = lane >> 3;
    const int pr = lane & 7;
    // A x4: lanes 0-7 (m0-7,k0-7), 8-15 (m8-15,k0-7), 16-23 (m0-7,k8-15), 24-31 (m8-15,k8-15)
    const uint32_t a_lane = smb + (uint32_t)((wm + (p & 1) * 8 + pr) * 80 + (p >> 1) * 16);
    // B x4: lanes 0-7 (n0-7,k0-7), 8-15 (n0-7,k8-15), 16-23 (n8-15,k0-7), 24-31 (n8-15,k8-15)
    const uint32_t b_lane = smb + OP_B + (uint32_t)((wn + (p >> 1) * 8 + pr) * 80 + (p & 1) * 16);

    float acc[2][8][4];
#pragma unroll
    for (int mi = 0; mi < 2; mi++)
#pragma unroll
        for (int ni = 0; ni < 8; ni++)
#pragma unroll
            for (int c = 0; c < 4; c++) acc[mi][ni][c] = 0.f;

    const int niter = K / TBK;
    ISSUE_TILE(0)
    if (niter > 1) ISSUE_TILE(1)
    if (niter > 2) ISSUE_TILE(2)

    for (int it = 0; it < niter; it++) {
        const int remafter = niter - it - 1;
        if (remafter >= 2)      asm volatile("cp.async.wait_group 2;");
        else if (remafter == 1) asm volatile("cp.async.wait_group 1;");
        else                    asm volatile("cp.async.wait_group 0;");
        __syncthreads();

        if (it + 3 < niter) ISSUE_TILE(it + 3)

        const uint32_t abase = a_lane + (uint32_t)(it & 3) * STG_B;
        const uint32_t bbase = b_lane + (uint32_t)(it & 3) * STG_B;
#pragma unroll
        for (int kk = 0; kk < 2; kk++) {           // two k16 blocks
            uint32_t af[2][4], bf[4][4];
#pragma unroll
            for (int mi = 0; mi < 2; mi++)
                LDSM4(af[mi][0], af[mi][1], af[mi][2], af[mi][3],
                      abase + mi * 1280 + kk * 32)
#pragma unroll
            for (int P = 0; P < 4; P++)
                LDSM4(bf[P][0], bf[P][1], bf[P][2], bf[P][3],
                      bbase + P * 1280 + kk * 32)
#pragma unroll
            for (int mi = 0; mi < 2; mi++)
#pragma unroll
                for (int ni = 0; ni < 8; ni++)
                    mma_f16(acc[mi][ni], af[mi],
                            bf[ni >> 1][(ni & 1) * 2],
                            bf[ni >> 1][(ni & 1) * 2 + 1]);
        }
        __syncthreads();
    }

    // ---------------- staged, coalesced epilogue ----------------
    float* Cs = sdyn;
#pragma unroll
    for (int mi = 0; mi < 2; mi++)
#pragma unroll
        for (int ni = 0; ni < 8; ni++)
#pragma unroll
            for (int cp = 0; cp < 2; cp++) {
                int row = wm + mi * 16 + gr + cp * 8;
                int col = wn + ni * 8 + 2 * gc;
                *(float2*)&Cs[row * 132 + col] =
                    make_float2(acc[mi][ni][cp * 2], acc[mi][ni][cp * 2 + 1]);
            }
    __syncthreads();

    const float* tmv = ga.tm[z];
#pragma unroll
    for (int ps = 0; ps < 16; ps++) {
        int row  = ps * 8 + wid;
        int col  = lane * 4;
        int grow = bm + row;
        int gcol = bn + col;
        if (gcol + 3 < N) {
            float4 v = *(float4*)&Cs[row * 132 + col];
            if (ep == EP_TANH) {
                v.x = tanhf(v.x); v.y = tanhf(v.y);
                v.z = tanhf(v.z); v.w = tanhf(v.w);
            } else if (ep == EP_SILU) {
                v.x = v.x / (1.f + expf(-v.x)); v.y = v.y / (1.f + expf(-v.y));
                v.z = v.z / (1.f + expf(-v.z)); v.w = v.w / (1.f + expf(-v.w));
            } else if (ep == EP_EXPW) {
                v.x = expf(ga.bias[gcol]     + v.x);
                v.y = expf(ga.bias[gcol + 1] + v.y);
                v.z = expf(ga.bias[gcol + 2] + v.z);
                v.w = expf(ga.bias[gcol + 3] + v.w);
            } else if (ep == EP_MIX) {
                size_t ix = (size_t)grow * CC + gcol;
                float4 x4  = *(const float4*)(ga.x + ix);
                float4 xx4 = *(const float4*)(ga.xx + ix);
                float4 t4  = *(const float4*)(tmv + gcol);
                v.x = fmaf(xx4.x, t4.x + v.x, x4.x);
                v.y = fmaf(xx4.y, t4.y + v.y, x4.y);
                v.z = fmaf(xx4.z, t4.z + v.z, x4.z);
                v.w = fmaf(xx4.w, t4.w + v.w, x4.w);
            }
            if (chf) {
                __half* Ch = (__half*)ga.C[z];
                *(__half2*)&Ch[(size_t)grow * N + gcol]     = __floats2half2_rn(v.x, v.y);
                *(__half2*)&Ch[(size_t)grow * N + gcol + 2] = __floats2half2_rn(v.z, v.w);
            } else {
                float* Cf = (float*)ga.C[z];
                *(float4*)&Cf[(size_t)grow * N + gcol] = v;
            }
        } else if (gcol < N) {
            for (int e = 0; e < 4 && gcol + e < N; e++) {
                float v0 = Cs[row * 132 + col + e];
                if (ep == EP_TANH) v0 = tanhf(v0);
                else if (ep == EP_SILU) v0 = v0 / (1.f + expf(-v0));
                else if (ep == EP_EXPW) v0 = expf(ga.bias[gcol + e] + v0);
                else if (ep == EP_MIX) {
                    size_t ix = (size_t)grow * CC + gcol + e;
                    v0 = fmaf(ga.xx[ix], tmv[gcol + e] + v0, ga.x[ix]);
                }
                if (chf) ((__half*)ga.C[z])[(size_t)grow * N + gcol + e] = __float2half_rn(v0);
                else     ((float*)ga.C[z])[(size_t)grow * N + gcol + e] = v0;
            }
        }
    }
}

// ------------------------- q_shift + maa_x mix -------------------------------
// xx fp32 (epilogue math), xxx fp16 (GEMM A operand)
__global__ void shift_kernel(const float* __restrict__ x,
                             const float* __restrict__ tmx,
                             float* __restrict__ xx,
                             __half* __restrict__ xxx)
{
    int idx = blockIdx.x * blockDim.x + threadIdx.x;
    if (idx >= MM * (CC/4)) return;
    int c4i = idx % (CC/4);
    int m   = idx / (CC/4);
    int c   = c4i * 4;
    int b = m >> 10;
    int t = m & 1023;
    int hh = t >> 5;
    int w  = t & 31;
    int q  = c / C4;
    int sh = hh + ((q == 2) ? -1 : (q == 3) ? 1 : 0);
    int sw = w  + ((q == 0) ? -1 : (q == 1) ? 1 : 0);
    float4 xs = make_float4(0.f, 0.f, 0.f, 0.f);
    if (sh >= 0 && sh < HP_ && sw >= 0 && sw < WP_)
        xs = *(const float4*)(x + ((size_t)((b << 10) + (sh << 5) + sw)) * CC + c);
    float4 xv = ((const float4*)x)[idx];
    float4 tm = *(const float4*)(tmx + c);
    float4 d;
    d.x = xs.x - xv.x; d.y = xs.y - xv.y; d.z = xs.z - xv.z; d.w = xs.w - xv.w;
    float o0 = fmaf(d.x, tm.x, xv.x), o1 = fmaf(d.y, tm.y, xv.y);
    float o2 = fmaf(d.z, tm.z, xv.z), o3 = fmaf(d.w, tm.w, xv.w);
    ((float4*)xx)[idx] = d;
    ((__half2*)xxx)[idx * 2]     = __floats2half2_rn(o0, o1);
    ((__half2*)xxx)[idx * 2 + 1] = __floats2half2_rn(o2, o3);
}

// ----------------------------- chunked WKV6 (R5 version) --------------------
__global__ void __launch_bounds__(256) wkv_chunk_kernel(
    const float* __restrict__ r, const float* __restrict__ k,
    const float* __restrict__ v, const float* __restrict__ ew,
    const float* __restrict__ u, float* __restrict__ y)
{
    __shared__ float sr[CL][36], sk[CL][36], sv[CL][36], se[CL][36];
    __shared__ float scum[CL][36], sKtT[HSZ][36], satt[CL][36], sS[HSZ][36];
    __shared__ float sdiag[CL], scend[HSZ], su[HSZ];

    const int head = blockIdx.x;
    const int b = head / NHD, h = head % NHD;
    const int tid  = threadIdx.x;
    const int lane = tid & 31;
    const int wid  = tid >> 5;
    const int tld = tid >> 3;
    const int jld = (tid & 7) << 2;

    if (tid < HSZ) su[tid] = u[h * HSZ + tid];
    for (int zz = tid; zz < HSZ * 36; zz += 256) ((float*)sS)[zz] = 0.f;

    const size_t base = (size_t)b * TT * CC + (size_t)h * HSZ;

    size_t g0 = base + (size_t)tld * CC + jld;
    float4 r4 = *(const float4*)(r  + g0);
    float4 k4 = *(const float4*)(k  + g0);
    float4 v4 = *(const float4*)(v  + g0);
    float4 e4 = *(const float4*)(ew + g0);
    __syncthreads();

    for (int c0 = 0; c0 < TT; c0 += CL) {
        *(float4*)&sr[tld][jld] = r4;
        *(float4*)&sk[tld][jld] = k4;
        *(float4*)&sv[tld][jld] = v4;
        *(float4*)&se[tld][jld] = e4;
        __syncthreads();

#pragma unroll
        for (int q = 0; q < 4; q++) {
            int j = wid * 4 + q;
            float vv = se[lane][j];
#pragma unroll
            for (int off = 1; off < 32; off <<= 1) {
                float nb = __shfl_up_sync(0xffffffffu, vv, off);
                if (lane >= off) vv += nb;
            }
            scum[lane][j] = vv;
            if (lane == 31) scend[j] = vv;
        }
        {
            float pp = 0.f;
#pragma unroll
            for (int e = 0; e < 4; e++)
                pp += sr[tld][jld + e] * su[jld + e] * sk[tld][jld + e];
            pp += __shfl_xor_sync(0xffffffffu, pp, 1);
            pp += __shfl_xor_sync(0xffffffffu, pp, 2);
            pp += __shfl_xor_sync(0xffffffffu, pp, 4);
            if ((lane & 7) == 0) sdiag[tld] = pp;
        }
        __syncthreads();

#pragma unroll
        for (int e = 0; e < 4; e++) {
            int j = jld + e;
            float cum = scum[tld][j];
            float ev  = se[tld][j];
            float rw  = sr[tld][j];
            float kw  = sk[tld][j];
            sr[tld][j]   = rw * expf(ev - cum);
            sKtT[j][tld] = kw * expf(cum);
            scum[tld][j] = kw * expf(cum - scend[j]);
        }
        __syncthreads();

        {
            const int t = tld, t4 = jld;
            float a0 = 0.f, a1 = 0.f, a2 = 0.f, a3 = 0.f;
#pragma unroll
            for (int j = 0; j < HSZ; j++) {
                float rt = sr[t][j];
                float4 kt = *(const float4*)&sKtT[j][t4];
                a0 = fmaf(rt, kt.x, a0); a1 = fmaf(rt, kt.y, a1);
                a2 = fmaf(rt, kt.z, a2); a3 = fmaf(rt, kt.w, a3);
            }
            float dv = sdiag[t];
            satt[t][t4+0] = (t4+0 < t) ? a0 : ((t4+0 == t) ? dv : 0.f);
            satt[t][t4+1] = (t4+1 < t) ? a1 : ((t4+1 == t) ? dv : 0.f);
            satt[t][t4+2] = (t4+2 < t) ? a2 : ((t4+2 == t) ? dv : 0.f);
            satt[t][t4+3] = (t4+3 < t) ? a3 : ((t4+3 == t) ? dv : 0.f);
        }
        __syncthreads();

        if (c0 + CL < TT) {
            size_t gn = base + (size_t)(c0 + CL + tld) * CC + jld;
            r4 = *(const float4*)(r  + gn);
            k4 = *(const float4*)(k  + gn);
            v4 = *(const float4*)(v  + gn);
            e4 = *(const float4*)(ew + gn);
        }

        {
            const int t = tld, i4 = jld;
            float4 acc = make_float4(0.f, 0.f, 0.f, 0.f);
#pragma unroll
            for (int tau = 0; tau < CL; tau++) {
                float at = satt[t][tau];
                float4 vv = *(const float4*)&sv[tau][i4];
                acc.x = fmaf(at, vv.x, acc.x); acc.y = fmaf(at, vv.y, acc.y);
                acc.z = fmaf(at, vv.z, acc.z); acc.w = fmaf(at, vv.w, acc.w);
            }
#pragma unroll
            for (int j = 0; j < HSZ; j++) {
                float rt = sr[t][j];
                float4 sj = *(const float4*)&sS[j][i4];
                acc.x = fmaf(rt, sj.x, acc.x); acc.y = fmaf(rt, sj.y, acc.y);
                acc.z = fmaf(rt, sj.z, acc.z); acc.w = fmaf(rt, sj.w, acc.w);
            }
            *(float4*)(y + base + (size_t)(c0 + t) * CC + i4) = acc;
        }
        __syncthreads();

        {
            const int j = tld, i4 = jld;
            float dend = expf(-scend[j]);
            float4 s = *(const float4*)&sS[j][i4];
            s.x *= dend; s.y *= dend; s.z *= dend; s.w *= dend;
#pragma unroll
            for (int tau = 0; tau < CL; tau++) {
                float kh = scum[tau][j];
                float4 vv = *(const float4*)&sv[tau][i4];
                s.x = fmaf(kh, vv.x, s.x); s.y = fmaf(kh, vv.y, s.y);
                s.z = fmaf(kh, vv.z, s.z); s.w = fmaf(kh, vv.w, s.w);
            }
            *(float4*)&sS[j][i4] = s;
        }
        __syncthreads();
    }
}

// --------------------------- LayerNorm * gate (half out) --------------------
__global__ void __launch_bounds__(256) ln_gate_kernel(
    const float* __restrict__ y, const float* __restrict__ g,
    const float* __restrict__ lw, const float* __restrict__ lb,
    __half* __restrict__ out)
{
    __shared__ float red[8];
    int m = blockIdx.x;
    int t = threadIdx.x;
    size_t base = (size_t)m * CC;
    float v0 = y[base + t], v1 = y[base + t + 256], v2 = y[base + t + 512];
    float s = v0 + v1 + v2;
#pragma unroll
    for (int o = 16; o; o >>= 1) s += __shfl_xor_sync(0xffffffffu, s, o);
    if ((t & 31) == 0) red[t >> 5] = s;
    __syncthreads();
    float tot = red[0]+red[1]+red[2]+red[3]+red[4]+red[5]+red[6]+red[7];
    float mu = tot * (1.f / CC);
    float d0 = v0 - mu, d1 = v1 - mu, d2 = v2 - mu;
    float q = d0*d0 + d1*d1 + d2*d2;
#pragma unroll
    for (int o = 16; o; o >>= 1) q += __shfl_xor_sync(0xffffffffu, q, o);
    __syncthreads();
    if ((t & 31) == 0) red[t >> 5] = q;
    __syncthreads();
    float var = (red[0]+red[1]+red[2]+red[3]+red[4]+red[5]+red[6]+red[7]) * (1.f / CC);
    float inv = rsqrtf(var + 1e-5f);
    out[base + t]       = __float2half_rn((d0 * inv * lw[t]       + lb[t])       * g[base + t]);
    out[base + t + 256] = __float2half_rn((d1 * inv * lw[t + 256] + lb[t + 256]) * g[base + t + 256]);
    out[base + t + 512] = __float2half_rn((d2 * inv * lw[t + 512] + lb[t + 512]) * g[base + t + 512]);
}

// ------------------------------- launcher -----------------------------------
extern "C" void kernel_launch(void* const* d_in, const int* in_sizes, int n_in,
                              void* d_out, int out_size)
{
    const float* x    = (const float*)d_in[0];
    const float* tmx  = (const float*)d_in[1];
    const float* tmw  = (const float*)d_in[2];
    const float* tmk  = (const float*)d_in[3];
    const float* tmv  = (const float*)d_in[4];
    const float* tmr  = (const float*)d_in[5];
    const float* tmg  = (const float*)d_in[6];
    const float* w1   = (const float*)d_in[7];
    const float* w2   = (const float*)d_in[8];
    const float* tdec = (const float*)d_in[9];
    const float* dw1  = (const float*)d_in[10];
    const float* dw2  = (const float*)d_in[11];
    const float* faaa = (const float*)d_in[12];
    const float* W_r  = (const float*)d_in[13];
    const float* W_k  = (const float*)d_in[14];
    const float* W_v  = (const float*)d_in[15];
    const float* W_g  = (const float*)d_in[16];
    const float* W_o  = (const float*)d_in[17];
    const float* lnw  = (const float*)d_in[18];
    const float* lnb  = (const float*)d_in[19];
    float* out = (float*)d_out;

    static int attr_set = 0;
    if (!attr_set) {
        cudaFuncSetAttribute(gemm_kernel,
                             cudaFuncAttributeMaxDynamicSharedMemorySize,
                             GEMM_DSMEM);
        attr_set = 1;
    }

    float* buf = nullptr;
    cudaGetSymbolAddress((void**)&buf, g_scratch);

    // fp32 buffers
    float* xx  = buf;                     // slot 0 (also reused for ln half)
    float* rr  = buf + 7 * SSLOT;
    float* kk  = buf + 8 * SSLOT;
    float* vv  = buf + 9 * SSLOT;
    float* gg  = buf + 10 * SSLOT;
    float* eww = buf + 11 * SSLOT;
    float* yy  = buf + 12 * SSLOT;

    // fp16 buffers (cast views into float slots)
    __half* xxx = (__half*)(buf + 1 * SSLOT);
    __half* m0  = (__half*)(buf + 2 * SSLOT);
    __half* m1  = (__half*)(buf + 3 * SSLOT);
    __half* m2  = (__half*)(buf + 4 * SSLOT);
    __half* m3  = (__half*)(buf + 5 * SSLOT);
    __half* m4  = (__half*)(buf + 6 * SSLOT);
    __half* G1  = (__half*)(buf + 13 * SSLOT);            // 4096 x 160 half
    __half* ww  = (__half*)(buf + 13 * SSLOT + 1048576);  // 4096 x 64 half
    __half* ln  = (__half*)xx;                            // reuse slot 0

    // fp16 transposed weights
    __half* Wt_r = (__half*)(buf + 14 * SSLOT);
    __half* Wt_k = Wt_r + 589824;
    __half* Wt_v = Wt_k + 589824;
    __half* Wt_g = Wt_v + 589824;
    __half* Wt_o = Wt_g + 589824;
    __half* w1t  = Wt_o + 589824;          // 256 x 768
    __half* dw1t = (__half*)(buf + 15 * SSLOT);   // 128 x 768
    __half* dw2t = dw1t + 98304;           // 768 x 64
    __half* w2t  = dw2t + 49152;           // 5 x 768 x 32

    const int EW4 = (MM * (CC/4) + 255) / 256;

    // 0) weight transposes + fp16 convert
    {
        TArgs ta = {};
        const float* srcs[NTR] = {W_r, W_k, W_v, W_g, W_o, w1, dw1, dw2,
                                  w2, w2 + 32*768, w2 + 2*32*768,
                                  w2 + 3*32*768, w2 + 4*32*768};
        __half* dsts[NTR] = {Wt_r, Wt_k, Wt_v, Wt_g, Wt_o, w1t, dw1t, dw2t,
                             w2t, w2t + 24576, w2t + 2*24576,
                             w2t + 3*24576, w2t + 4*24576};
        int Ks[NTR]  = {768,768,768,768,768, 768, 768, 64, 32,32,32,32,32};
        int Ns[NTR]  = {768,768,768,768,768, 160,  64, 768, 768,768,768,768,768};
        int Nps[NTR] = {768,768,768,768,768, 256, 128, 768, 768,768,768,768,768};
        for (int i = 0; i < NTR; i++) {
            ta.src[i] = srcs[i]; ta.dst[i] = dsts[i];
            ta.K[i] = Ks[i]; ta.N[i] = Ns[i]; ta.Np[i] = Nps[i];
        }
        transpose_kernel<<<dim3(24, 24, NTR), dim3(32, 8)>>>(ta);
    }

    // 1) q-shift + maa_x mix
    shift_kernel<<<EW4, 256>>>(x, tmx, xx, xxx);

    // 2) G1 = tanh(xxx @ w1)  -> half
    {
        GArgs a = {};
        a.A[0] = xxx; a.B[0] = w1t; a.C[0] = G1;
        a.ep[0] = EP_TANH; a.ch[0] = 1; a.N[0] = 160; a.lda[0] = CC; a.K = CC;
        gemm_kernel<<<dim3(2, 32, 1), 256, GEMM_DSMEM>>>(a);
    }

    // 3) 5 mix GEMMs (K=32), fused mix epilogue -> half m*
    {
        GArgs a = {};
        __half* mouts[5] = {m0, m1, m2, m3, m4};
        const float* tms[5] = {tmw, tmk, tmv, tmr, tmg};
        for (int q = 0; q < 5; q++) {
            a.A[q] = G1 + q * 32;
            a.B[q] = w2t + (size_t)q * 24576;
            a.C[q] = mouts[q];
            a.tm[q] = tms[q];
            a.ep[q] = EP_MIX; a.ch[q] = 1; a.N[q] = CC; a.lda[q] = 160;
        }
        a.K = 32; a.x = x; a.xx = xx;
        gemm_kernel<<<dim3(6, 32, 5), 256, GEMM_DSMEM>>>(a);
    }

    // 4) grouped projections: r,k,v,g (fp32 out) + dw1 (half out), K=768
    {
        GArgs a = {};
        a.A[0] = m3; a.B[0] = Wt_r; a.C[0] = rr; a.ep[0] = EP_NONE; a.ch[0] = 0; a.N[0] = CC; a.lda[0] = CC;
        a.A[1] = m1; a.B[1] = Wt_k; a.C[1] = kk; a.ep[1] = EP_NONE; a.ch[1] = 0; a.N[1] = CC; a.lda[1] = CC;
        a.A[2] = m2; a.B[2] = Wt_v; a.C[2] = vv; a.ep[2] = EP_NONE; a.ch[2] = 0; a.N[2] = CC; a.lda[2] = CC;
        a.A[3] = m4; a.B[3] = Wt_g; a.C[3] = gg; a.ep[3] = EP_SILU; a.ch[3] = 0; a.N[3] = CC; a.lda[3] = CC;
        a.A[4] = m0; a.B[4] = dw1t; a.C[4] = ww; a.ep[4] = EP_TANH; a.ch[4] = 1; a.N[4] = 64; a.lda[4] = CC;
        a.K = CC;
        gemm_kernel<<<dim3(6, 32, 5), 256, GEMM_DSMEM>>>(a);
    }

    // 5) eww = exp(tdec + ww @ dw2)  (fp32 out)
    {
        GArgs a = {};
        a.A[0] = ww; a.B[0] = dw2t; a.C[0] = eww;
        a.ep[0] = EP_EXPW; a.ch[0] = 0; a.N[0] = CC; a.lda[0] = 64; a.K = 64;
        a.bias = tdec;
        gemm_kernel<<<dim3(6, 32, 1), 256, GEMM_DSMEM>>>(a);
    }

    // 6) chunked WKV6 (96 blocks)
    wkv_chunk_kernel<<<BBATCH * NHD, 256>>>(rr, kk, vv, eww, faaa, yy);

    // 7) LayerNorm * gate -> half ln
    ln_gate_kernel<<<MM, 256>>>(yy, gg, lnw, lnb, ln);

    // 8) output projection (fp32 out)
    {
        GArgs a = {};
        a.A[0] = ln; a.B[0] = Wt_o; a.C[0] = out;
        a.ep[0] = EP_NONE; a.ch[0] = 0; a.N[0] = CC; a.lda[0] = CC; a.K = CC;
        gemm_kernel<<<dim3(6, 32, 1), 256, GEMM_DSMEM>>>(a);
    }

    (void)in_sizes; (void)n_in; (void)out_size;
}

// round 10
// speedup vs baseline: 1.6266x; 1.0845x over previous
#include <cuda_runtime.h>
#include <cuda_fp16.h>
#include <math.h>
#include <stdint.h>

// ----------------------------- problem constants ---------------------------
#define CC   768
#define TT   1024
#define BBATCH 4
#define MM   (BBATCH*TT)
#define NHD  24
#define HSZ  32
#define HP_  32
#define WP_  32
#define C4   (CC/4)
#define CL   32
#define NCH  32                  // chunks per sequence

#define SSLOT 3145728ull
__device__ float g_scratch[16ull*SSLOT];

enum { EP_NONE = 0, EP_TANH = 1, EP_SILU = 2, EP_EXPW = 3, EP_MIX = 4 };

// ----------------------------- MMA helpers ---------------------------------
__device__ __forceinline__ void mma_f16(float acc[4], const uint32_t a[4],
                                        const uint32_t b0, const uint32_t b1) {
    asm volatile(
        "mma.sync.aligned.m16n8k16.row.col.f32.f16.f16.f32 "
        "{%0,%1,%2,%3}, {%4,%5,%6,%7}, {%8,%9}, {%0,%1,%2,%3};"
        : "+f"(acc[0]), "+f"(acc[1]), "+f"(acc[2]), "+f"(acc[3])
        : "r"(a[0]), "r"(a[1]), "r"(a[2]), "r"(a[3]), "r"(b0), "r"(b1));
}

#define LDSM4(d0, d1, d2, d3, addr)                                           \
    asm volatile("ldmatrix.sync.aligned.m8n8.x4.shared.b16 {%0,%1,%2,%3}, [%4];" \
                 : "=r"(d0), "=r"(d1), "=r"(d2), "=r"(d3) : "r"(addr));

__device__ __forceinline__ void cpasync16(uint32_t saddr, const void* gptr) {
    asm volatile("cp.async.cg.shared.global [%0], [%1], 16;"
                 :: "r"(saddr), "l"(gptr));
}

// --------------------- weight transpose + fp16 convert ----------------------
#define NTR 8
struct TArgs {
    const float* src[NTR];
    __half*      dst[NTR];
    int K[NTR];
    int N[NTR];
    int Np[NTR];
};

__global__ void transpose_kernel(TArgs ta)
{
    __shared__ float tile[32][33];
    const int z = blockIdx.z;
    const int K = ta.K[z], N = ta.N[z], Np = ta.Np[z];
    const int x0 = blockIdx.x * 32;
    const int y0 = blockIdx.y * 32;
    if (x0 >= Np || y0 >= K) return;
    const float* src = ta.src[z];
    __half* dst = ta.dst[z];
    const int tx = threadIdx.x, ty = threadIdx.y;
#pragma unroll
    for (int j = 0; j < 4; j++) {
        int k = y0 + ty + 8 * j;
        int n = x0 + tx;
        tile[ty + 8 * j][tx] = (n < N) ? src[(size_t)k * N + n] : 0.f;
    }
    __syncthreads();
#pragma unroll
    for (int j = 0; j < 4; j++) {
        int n = x0 + ty + 8 * j;
        int k = y0 + tx;
        dst[(size_t)n * K + k] = __float2half_rn(tile[tx][ty + 8 * j]);
    }
}

// ---------------- build block-diagonal mix weight Bmix[3840][160] -----------
// Bmix[z*768+c][z*32+e] = w2[z][e][c]; zero elsewhere.
__global__ void build_bmix_kernel(const float* __restrict__ w2,
                                  __half* __restrict__ bmix)
{
    int idx = blockIdx.x * blockDim.x + threadIdx.x;   // over 3840*160
    if (idx >= 3840 * 160) return;
    int row = idx / 160;
    int kcol = idx % 160;
    int q = row / 768;
    int c = row % 768;
    float v = 0.f;
    if (kcol / 32 == q)
        v = w2[(size_t)q * 32 * 768 + (size_t)(kcol % 32) * 768 + c];
    bmix[idx] = __float2half_rn(v);
}

// -------------------------- grouped FP16 MMA GEMM ---------------------------
struct GArgs {
    const __half* A[5];
    const __half* B[5];
    void*         C[5];
    const float*  tm[5];
    int ep[5];
    int ch[5];       // 1 = C is half
    int N[5];
    int ldc[5];
    int lda[5];
    int K;
    const float* x;
    const float* xx;
    const float* bias;
};

#define TBM 128
#define TBN 128
#define TBK 32
#define OP_B   10240u
#define STG_B  20480u
#define GEMM_DSMEM 81920

#define ISSUE_TILE(tile)                                                       \
    {                                                                          \
        int k0_ = (tile) * TBK;                                                \
        uint32_t sa_ = smb + ((tile) & 3) * STG_B;                             \
        uint32_t sb_ = sa_ + OP_B;                                             \
        int row_ = tid >> 1;                                                   \
        int te_  = (tid & 1) * 16;                                             \
        const __half* Ap_ = A + (size_t)(bm + row_) * lda + k0_ + te_;         \
        cpasync16(sa_ + row_ * 80 + te_ * 2,      Ap_);                        \
        cpasync16(sa_ + row_ * 80 + te_ * 2 + 16, Ap_ + 8);                    \
        const __half* Bp_ = B + (size_t)(bn + row_) * K + k0_ + te_;           \
        cpasync16(sb_ + row_ * 80 + te_ * 2,      Bp_);                        \
        cpasync16(sb_ + row_ * 80 + te_ * 2 + 16, Bp_ + 8);                    \
        asm volatile("cp.async.commit_group;");                                \
    }

__global__ void __launch_bounds__(256, 2) gemm_kernel(GArgs ga)
{
    extern __shared__ float sdyn[];

    const int z = blockIdx.z;
    const __half* __restrict__ A = ga.A[z];
    const __half* __restrict__ B = ga.B[z];
    const int N   = ga.N[z];
    const int ldc = ga.ldc[z];
    const int lda = ga.lda[z];
    const int K   = ga.K;
    const int ep  = ga.ep[z];
    const int chf = ga.ch[z];

    const int bn = blockIdx.x * TBN;
    if (bn >= N) return;
    const int bm = blockIdx.y * TBM;
    const int zoff = (bn / 768) * 768;           // EP_MIX z-segment base

    const int tid  = threadIdx.x;
    const int lane = tid & 31;
    const int wid  = tid >> 5;
    const int gr = lane >> 2, gc = lane & 3;
    const int wm = (wid & 3) * 32;
    const int wn = (wid >> 2) * 64;

    const uint32_t smb = (uint32_t)__cvta_generic_to_shared(sdyn);

    const int p  = lane >> 3;
    const int pr = lane & 7;
    const uint32_t a_lane = smb + (uint32_t)((wm + (p & 1) * 8 + pr) * 80 + (p >> 1) * 16);
    const uint32_t b_lane = smb + OP_B + (uint32_t)((wn + (p >> 1) * 8 + pr) * 80 + (p & 1) * 16);

    float acc[2][8][4];
#pragma unroll
    for (int mi = 0; mi < 2; mi++)
#pragma unroll
        for (int ni = 0; ni < 8; ni++)
#pragma unroll
            for (int c = 0; c < 4; c++) acc[mi][ni][c] = 0.f;

    const int niter = K / TBK;
    ISSUE_TILE(0)
    if (niter > 1) ISSUE_TILE(1)
    if (niter > 2) ISSUE_TILE(2)

    for (int it = 0; it < niter; it++) {
        const int remafter = niter - it - 1;
        if (remafter >= 2)      asm volatile("cp.async.wait_group 2;");
        else if (remafter == 1) asm volatile("cp.async.wait_group 1;");
        else                    asm volatile("cp.async.wait_group 0;");
        __syncthreads();

        if (it + 3 < niter) ISSUE_TILE(it + 3)

        const uint32_t abase = a_lane + (uint32_t)(it & 3) * STG_B;
        const uint32_t bbase = b_lane + (uint32_t)(it & 3) * STG_B;
#pragma unroll
        for (int kk = 0; kk < 2; kk++) {
            uint32_t af[2][4], bf[4][4];
#pragma unroll
            for (int mi = 0; mi < 2; mi++)
                LDSM4(af[mi][0], af[mi][1], af[mi][2], af[mi][3],
                      abase + mi * 1280 + kk * 32)
#pragma unroll
            for (int P = 0; P < 4; P++)
                LDSM4(bf[P][0], bf[P][1], bf[P][2], bf[P][3],
                      bbase + P * 1280 + kk * 32)
#pragma unroll
            for (int mi = 0; mi < 2; mi++)
#pragma unroll
                for (int ni = 0; ni < 8; ni++)
                    mma_f16(acc[mi][ni], af[mi],
                            bf[ni >> 1][(ni & 1) * 2],
                            bf[ni >> 1][(ni & 1) * 2 + 1]);
        }
        __syncthreads();
    }

    // ---------------- staged, coalesced epilogue ----------------
    float* Cs = sdyn;
#pragma unroll
    for (int mi = 0; mi < 2; mi++)
#pragma unroll
        for (int ni = 0; ni < 8; ni++)
#pragma unroll
            for (int cp = 0; cp < 2; cp++) {
                int row = wm + mi * 16 + gr + cp * 8;
                int col = wn + ni * 8 + 2 * gc;
                *(float2*)&Cs[row * 132 + col] =
                    make_float2(acc[mi][ni][cp * 2], acc[mi][ni][cp * 2 + 1]);
            }
    __syncthreads();

    const float* tmv = ga.tm[bn / 768];
#pragma unroll
    for (int ps = 0; ps < 16; ps++) {
        int row  = ps * 8 + wid;
        int col  = lane * 4;
        int grow = bm + row;
        int gcol = bn + col;
        if (gcol + 3 < N) {
            float4 v = *(float4*)&Cs[row * 132 + col];
            if (ep == EP_TANH) {
                v.x = tanhf(v.x); v.y = tanhf(v.y);
                v.z = tanhf(v.z); v.w = tanhf(v.w);
            } else if (ep == EP_SILU) {
                v.x = v.x / (1.f + expf(-v.x)); v.y = v.y / (1.f + expf(-v.y));
                v.z = v.z / (1.f + expf(-v.z)); v.w = v.w / (1.f + expf(-v.w));
            } else if (ep == EP_EXPW) {
                v.x = expf(ga.bias[gcol]     + v.x);
                v.y = expf(ga.bias[gcol + 1] + v.y);
                v.z = expf(ga.bias[gcol + 2] + v.z);
                v.w = expf(ga.bias[gcol + 3] + v.w);
            } else if (ep == EP_MIX) {
                int ccol = gcol - zoff;
                size_t ix = (size_t)grow * CC + ccol;
                float4 x4  = *(const float4*)(ga.x + ix);
                float4 xx4 = *(const float4*)(ga.xx + ix);
                float4 t4  = *(const float4*)(tmv + ccol);
                v.x = fmaf(xx4.x, t4.x + v.x, x4.x);
                v.y = fmaf(xx4.y, t4.y + v.y, x4.y);
                v.z = fmaf(xx4.z, t4.z + v.z, x4.z);
                v.w = fmaf(xx4.w, t4.w + v.w, x4.w);
            }
            if (chf) {
                __half* Ch = (__half*)ga.C[z];
                *(__half2*)&Ch[(size_t)grow * ldc + gcol]     = __floats2half2_rn(v.x, v.y);
                *(__half2*)&Ch[(size_t)grow * ldc + gcol + 2] = __floats2half2_rn(v.z, v.w);
            } else {
                float* Cf = (float*)ga.C[z];
                *(float4*)&Cf[(size_t)grow * ldc + gcol] = v;
            }
        } else if (gcol < N) {
            for (int e = 0; e < 4 && gcol + e < N; e++) {
                float v0 = Cs[row * 132 + col + e];
                if (ep == EP_TANH) v0 = tanhf(v0);
                else if (ep == EP_SILU) v0 = v0 / (1.f + expf(-v0));
                else if (ep == EP_EXPW) v0 = expf(ga.bias[gcol + e] + v0);
                else if (ep == EP_MIX) {
                    size_t ix = (size_t)grow * CC + (gcol - zoff) + e;
                    v0 = fmaf(ga.xx[ix], tmv[(gcol - zoff) + e] + v0, ga.x[ix]);
                }
                if (chf) ((__half*)ga.C[z])[(size_t)grow * ldc + gcol + e] = __float2half_rn(v0);
                else     ((float*)ga.C[z])[(size_t)grow * ldc + gcol + e] = v0;
            }
        }
    }
}

// ------------------------- q_shift + maa_x mix -------------------------------
__global__ void shift_kernel(const float* __restrict__ x,
                             const float* __restrict__ tmx,
                             float* __restrict__ xx,
                             __half* __restrict__ xxx)
{
    int idx = blockIdx.x * blockDim.x + threadIdx.x;
    if (idx >= MM * (CC/4)) return;
    int c4i = idx % (CC/4);
    int m   = idx / (CC/4);
    int c   = c4i * 4;
    int b = m >> 10;
    int t = m & 1023;
    int hh = t >> 5;
    int w  = t & 31;
    int q  = c / C4;
    int sh = hh + ((q == 2) ? -1 : (q == 3) ? 1 : 0);
    int sw = w  + ((q == 0) ? -1 : (q == 1) ? 1 : 0);
    float4 xs = make_float4(0.f, 0.f, 0.f, 0.f);
    if (sh >= 0 && sh < HP_ && sw >= 0 && sw < WP_)
        xs = *(const float4*)(x + ((size_t)((b << 10) + (sh << 5) + sw)) * CC + c);
    float4 xv = ((const float4*)x)[idx];
    float4 tm = *(const float4*)(tmx + c);
    float4 d;
    d.x = xs.x - xv.x; d.y = xs.y - xv.y; d.z = xs.z - xv.z; d.w = xs.w - xv.w;
    float o0 = fmaf(d.x, tm.x, xv.x), o1 = fmaf(d.y, tm.y, xv.y);
    float o2 = fmaf(d.z, tm.z, xv.z), o3 = fmaf(d.w, tm.w, xv.w);
    ((float4*)xx)[idx] = d;
    ((__half2*)xxx)[idx * 2]     = __floats2half2_rn(o0, o1);
    ((__half2*)xxx)[idx * 2 + 1] = __floats2half2_rn(o2, o3);
}

// ------------------- WKV phase A: intra-chunk + U/d/R~ -----------------------
// block = (head, chunk). y gets intra-chunk att@V; gU/gD/gRt to global.
__global__ void __launch_bounds__(256) wkv_intra_kernel(
    const float* __restrict__ r, const float* __restrict__ k,
    const float* __restrict__ v, const float* __restrict__ ew,
    const float* __restrict__ u, float* __restrict__ y,
    float* __restrict__ gRt, float* __restrict__ gU, float* __restrict__ gD)
{
    __shared__ float sr[CL][36], sk[CL][36], sv[CL][36], se[CL][36];
    __shared__ float scum[CL][36], sKtT[HSZ][36], satt[CL][36];
    __shared__ float sdiag[CL], scend[HSZ], su[HSZ];

    const int hc = blockIdx.x;          // head*NCH + chunk
    const int head = hc >> 5;
    const int cch  = hc & 31;
    const int b = head / NHD, h = head % NHD;
    const int c0 = cch * CL;
    const int tid  = threadIdx.x;
    const int lane = tid & 31;
    const int wid  = tid >> 5;
    const int tld = tid >> 3;
    const int jld = (tid & 7) << 2;

    if (tid < HSZ) su[tid] = u[h * HSZ + tid];

    const size_t base = (size_t)b * TT * CC + (size_t)h * HSZ;
    size_t g0 = base + (size_t)(c0 + tld) * CC + jld;
    float4 r4 = *(const float4*)(r  + g0);
    float4 k4 = *(const float4*)(k  + g0);
    float4 v4 = *(const float4*)(v  + g0);
    float4 e4 = *(const float4*)(ew + g0);
    *(float4*)&sr[tld][jld] = r4;
    *(float4*)&sk[tld][jld] = k4;
    *(float4*)&sv[tld][jld] = v4;
    *(float4*)&se[tld][jld] = e4;
    __syncthreads();

    // cumsum over t (warp scan; warp wid owns j = wid*4..+3)
#pragma unroll
    for (int q = 0; q < 4; q++) {
        int j = wid * 4 + q;
        float vv = se[lane][j];
#pragma unroll
        for (int off = 1; off < 32; off <<= 1) {
            float nb = __shfl_up_sync(0xffffffffu, vv, off);
            if (lane >= off) vv += nb;
        }
        scum[lane][j] = vv;
        if (lane == 31) scend[j] = vv;
    }
    // diag
    {
        float pp = 0.f;
#pragma unroll
        for (int e = 0; e < 4; e++)
            pp += sr[tld][jld + e] * su[jld + e] * sk[tld][jld + e];
        pp += __shfl_xor_sync(0xffffffffu, pp, 1);
        pp += __shfl_xor_sync(0xffffffffu, pp, 2);
        pp += __shfl_xor_sync(0xffffffffu, pp, 4);
        if ((lane & 7) == 0) sdiag[tld] = pp;
    }
    __syncthreads();

    // transform: sr -> R~, sKtT -> Kt^T, scum -> Kh
#pragma unroll
    for (int e = 0; e < 4; e++) {
        int j = jld + e;
        float cum = scum[tld][j];
        float ev  = se[tld][j];
        float rw  = sr[tld][j];
        float kw  = sk[tld][j];
        sr[tld][j]   = rw * expf(ev - cum);
        sKtT[j][tld] = kw * expf(cum);
        scum[tld][j] = kw * expf(cum - scend[j]);
    }
    __syncthreads();

    // att = R~ @ Kt^T, masked
    {
        const int t = tld, t4 = jld;
        float a0 = 0.f, a1 = 0.f, a2 = 0.f, a3 = 0.f;
#pragma unroll
        for (int j = 0; j < HSZ; j++) {
            float rt = sr[t][j];
            float4 kt = *(const float4*)&sKtT[j][t4];
            a0 = fmaf(rt, kt.x, a0); a1 = fmaf(rt, kt.y, a1);
            a2 = fmaf(rt, kt.z, a2); a3 = fmaf(rt, kt.w, a3);
        }
        float dv = sdiag[t];
        satt[t][t4+0] = (t4+0 < t) ? a0 : ((t4+0 == t) ? dv : 0.f);
        satt[t][t4+1] = (t4+1 < t) ? a1 : ((t4+1 == t) ? dv : 0.f);
        satt[t][t4+2] = (t4+2 < t) ? a2 : ((t4+2 == t) ? dv : 0.f);
        satt[t][t4+3] = (t4+3 < t) ? a3 : ((t4+3 == t) ? dv : 0.f);
    }
    __syncthreads();

    // write R~ and d
    *(float4*)(gRt + (size_t)hc * 1024 + tld * 32 + jld) = *(float4*)&sr[tld][jld];
    if (tid < HSZ) gD[(size_t)hc * 32 + tid] = expf(-scend[tid]);

    // Y_intra = att @ V
    {
        const int t = tld, i4 = jld;
        float4 acc = make_float4(0.f, 0.f, 0.f, 0.f);
#pragma unroll
        for (int tau = 0; tau < CL; tau++) {
            float at = satt[t][tau];
            float4 vv = *(const float4*)&sv[tau][i4];
            acc.x = fmaf(at, vv.x, acc.x); acc.y = fmaf(at, vv.y, acc.y);
            acc.z = fmaf(at, vv.z, acc.z); acc.w = fmaf(at, vv.w, acc.w);
        }
        *(float4*)(y + base + (size_t)(c0 + t) * CC + i4) = acc;
    }

    // U = Kh^T @ V  (thread = (j=tld, i4))
    {
        const int j = tld, i4 = jld;
        float4 s = make_float4(0.f, 0.f, 0.f, 0.f);
#pragma unroll
        for (int tau = 0; tau < CL; tau++) {
            float kh = scum[tau][j];
            float4 vv = *(const float4*)&sv[tau][i4];
            s.x = fmaf(kh, vv.x, s.x); s.y = fmaf(kh, vv.y, s.y);
            s.z = fmaf(kh, vv.z, s.z); s.w = fmaf(kh, vv.w, s.w);
        }
        *(float4*)(gU + (size_t)hc * 1024 + j * 32 + i4) = s;
    }
}

// ------------------- WKV phase B: inter-chunk prefix scan --------------------
// 96 blocks x 1024 threads; thread = (j = tid>>5, i = tid&31).
// gS[head][c][j][i] = S_in for chunk c (state before chunk c).
__global__ void __launch_bounds__(1024) wkv_scan_kernel(
    const float* __restrict__ gU, const float* __restrict__ gD,
    float* __restrict__ gS)
{
    const int head = blockIdx.x;
    const int j = threadIdx.x >> 5;
    const int i = threadIdx.x & 31;
    float s = 0.f;
#pragma unroll
    for (int c = 0; c < NCH; c++) {
        size_t e = ((size_t)(head * NCH + c) * 32 + j) * 32 + i;
        gS[e] = s;
        float d = gD[(size_t)(head * NCH + c) * 32 + j];
        s = fmaf(d, s, gU[e]);
    }
}

// ------------------- WKV phase C: y += R~ @ S_in ----------------------------
__global__ void __launch_bounds__(256) wkv_inter_kernel(
    const float* __restrict__ gRt, const float* __restrict__ gS,
    float* __restrict__ y)
{
    __shared__ float srt[CL][36], ss[HSZ][36];

    const int hc = blockIdx.x;
    const int head = hc >> 5;
    const int cch  = hc & 31;
    const int b = head / NHD, h = head % NHD;
    const int c0 = cch * CL;
    const int tid = threadIdx.x;
    const int tld = tid >> 3;
    const int jld = (tid & 7) << 2;

    *(float4*)&srt[tld][jld] = *(const float4*)(gRt + (size_t)hc * 1024 + tld * 32 + jld);
    *(float4*)&ss[tld][jld]  = *(const float4*)(gS  + (size_t)hc * 1024 + tld * 32 + jld);
    __syncthreads();

    const size_t base = (size_t)b * TT * CC + (size_t)h * HSZ;
    const int t = tld, i4 = jld;
    float4 acc = *(float4*)(y + base + (size_t)(c0 + t) * CC + i4);
#pragma unroll
    for (int j = 0; j < HSZ; j++) {
        float rt = srt[t][j];
        float4 sj = *(const float4*)&ss[j][i4];
        acc.x = fmaf(rt, sj.x, acc.x); acc.y = fmaf(rt, sj.y, acc.y);
        acc.z = fmaf(rt, sj.z, acc.z); acc.w = fmaf(rt, sj.w, acc.w);
    }
    *(float4*)(y + base + (size_t)(c0 + t) * CC + i4) = acc;
}

// --------------------------- LayerNorm * gate (half out) --------------------
__global__ void __launch_bounds__(256) ln_gate_kernel(
    const float* __restrict__ y, const float* __restrict__ g,
    const float* __restrict__ lw, const float* __restrict__ lb,
    __half* __restrict__ out)
{
    __shared__ float red[8];
    int m = blockIdx.x;
    int t = threadIdx.x;
    size_t base = (size_t)m * CC;
    float v0 = y[base + t], v1 = y[base + t + 256], v2 = y[base + t + 512];
    float s = v0 + v1 + v2;
#pragma unroll
    for (int o = 16; o; o >>= 1) s += __shfl_xor_sync(0xffffffffu, s, o);
    if ((t & 31) == 0) red[t >> 5] = s;
    __syncthreads();
    float tot = red[0]+red[1]+red[2]+red[3]+red[4]+red[5]+red[6]+red[7];
    float mu = tot * (1.f / CC);
    float d0 = v0 - mu, d1 = v1 - mu, d2 = v2 - mu;
    float q = d0*d0 + d1*d1 + d2*d2;
#pragma unroll
    for (int o = 16; o; o >>= 1) q += __shfl_xor_sync(0xffffffffu, q, o);
    __syncthreads();
    if ((t & 31) == 0) red[t >> 5] = q;
    __syncthreads();
    float var = (red[0]+red[1]+red[2]+red[3]+red[4]+red[5]+red[6]+red[7]) * (1.f / CC);
    float inv = rsqrtf(var + 1e-5f);
    out[base + t]       = __float2half_rn((d0 * inv * lw[t]       + lb[t])       * g[base + t]);
    out[base + t + 256] = __float2half_rn((d1 * inv * lw[t + 256] + lb[t + 256]) * g[base + t + 256]);
    out[base + t + 512] = __float2half_rn((d2 * inv * lw[t + 512] + lb[t + 512]) * g[base + t + 512]);
}

// ------------------------------- launcher -----------------------------------
extern "C" void kernel_launch(void* const* d_in, const int* in_sizes, int n_in,
                              void* d_out, int out_size)
{
    const float* x    = (const float*)d_in[0];
    const float* tmx  = (const float*)d_in[1];
    const float* tmw  = (const float*)d_in[2];
    const float* tmk  = (const float*)d_in[3];
    const float* tmv  = (const float*)d_in[4];
    const float* tmr  = (const float*)d_in[5];
    const float* tmg  = (const float*)d_in[6];
    const float* w1   = (const float*)d_in[7];
    const float* w2   = (const float*)d_in[8];
    const float* tdec = (const float*)d_in[9];
    const float* dw1  = (const float*)d_in[10];
    const float* dw2  = (const float*)d_in[11];
    const float* faaa = (const float*)d_in[12];
    const float* W_r  = (const float*)d_in[13];
    const float* W_k  = (const float*)d_in[14];
    const float* W_v  = (const float*)d_in[15];
    const float* W_g  = (const float*)d_in[16];
    const float* W_o  = (const float*)d_in[17];
    const float* lnw  = (const float*)d_in[18];
    const float* lnb  = (const float*)d_in[19];
    float* out = (float*)d_out;

    static int attr_set = 0;
    if (!attr_set) {
        cudaFuncSetAttribute(gemm_kernel,
                             cudaFuncAttributeMaxDynamicSharedMemorySize,
                             GEMM_DSMEM);
        attr_set = 1;
    }

    float* buf = nullptr;
    cudaGetSymbolAddress((void**)&buf, g_scratch);

    // fp32 buffers
    float* xx  = buf;                               // slot 0
    float* gRt = buf + 5 * SSLOT;                   // 96*32*1024 = SSLOT exactly
    float* gU  = buf + 6 * SSLOT;
    float* rr  = buf + 7 * SSLOT;
    float* kk  = buf + 8 * SSLOT;
    float* vv  = buf + 9 * SSLOT;
    float* gg  = buf + 10 * SSLOT;
    float* eww = buf + 11 * SSLOT;
    float* yy  = buf + 12 * SSLOT;
    float* gS  = buf + 1 * SSLOT + 1572864;         // upper half of slot 1... (see note)

    // fp16 buffers
    __half* xxx  = (__half*)(buf + 1 * SSLOT);      // 4096x768 half = 6.3MB (lower half of slot 1)
    __half* mAll = (__half*)(buf + 2 * SSLOT);      // 4096x3840 half = 31.5MB (slots 2-4)
    __half* G1   = (__half*)(buf + 13 * SSLOT);                 // 4096x160 half
    __half* ww   = (__half*)(buf + 13 * SSLOT + 393216);        // 4096x64 half
    float*  gD   = buf + 13 * SSLOT + 524288;                   // 96*32*32 fp32
    __half* bmix = (__half*)(buf + 13 * SSLOT + 786432);        // 3840x160 half
    __half* ln   = (__half*)xx;                                  // reuse slot 0

    // NOTE on gS: xxx occupies slot1[0 .. 1572864 floats) as halves; gS needs
    // 3145728 floats. Give gS its own region: slot 15 upper area is free.
    gS = buf + 15 * SSLOT;                          // dw1t/dw2t moved to slot-13 tail? no:
    // dw1t/dw2t live in slot 14 tail instead (see below).

    // fp16 transposed weights (slot 14 + slot 13 tail)
    __half* Wt_r = (__half*)(buf + 14 * SSLOT);
    __half* Wt_k = Wt_r + 589824;
    __half* Wt_v = Wt_k + 589824;
    __half* Wt_g = Wt_v + 589824;
    __half* Wt_o = Wt_g + 589824;
    __half* w1t  = Wt_o + 589824;                        // 256x768
    __half* dw1t = (__half*)(buf + 13 * SSLOT + 1100000); // 128x768 half
    __half* dw2t = dw1t + 98304;                          // 768x64 half

    const int EW4 = (MM * (CC/4) + 255) / 256;

    // 0) weight transposes + fp16 convert, plus block-diagonal mix weight
    {
        TArgs ta = {};
        const float* srcs[NTR] = {W_r, W_k, W_v, W_g, W_o, w1, dw1, dw2};
        __half* dsts[NTR] = {Wt_r, Wt_k, Wt_v, Wt_g, Wt_o, w1t, dw1t, dw2t};
        int Ks[NTR]  = {768,768,768,768,768, 768, 768, 64};
        int Ns[NTR]  = {768,768,768,768,768, 160,  64, 768};
        int Nps[NTR] = {768,768,768,768,768, 256, 128, 768};
        for (int i = 0; i < NTR; i++) {
            ta.src[i] = srcs[i]; ta.dst[i] = dsts[i];
            ta.K[i] = Ks[i]; ta.N[i] = Ns[i]; ta.Np[i] = Nps[i];
        }
        transpose_kernel<<<dim3(24, 24, NTR), dim3(32, 8)>>>(ta);
        build_bmix_kernel<<<(3840*160 + 255)/256, 256>>>(w2, bmix);
    }

    // 1) q-shift + maa_x mix
    shift_kernel<<<EW4, 256>>>(x, tmx, xx, xxx);

    // 2) G1 = tanh(xxx @ w1)  -> half
    {
        GArgs a = {};
        a.A[0] = xxx; a.B[0] = w1t; a.C[0] = G1;
        a.ep[0] = EP_TANH; a.ch[0] = 1; a.N[0] = 160; a.ldc[0] = 160;
        a.lda[0] = CC; a.K = CC;
        gemm_kernel<<<dim3(2, 32, 1), 256, GEMM_DSMEM>>>(a);
    }

    // 3) fused mix GEMM: mAll[4096][3840] = EP_MIX( G1 @ Bmix^T )
    {
        GArgs a = {};
        a.A[0] = G1; a.B[0] = bmix; a.C[0] = mAll;
        a.ep[0] = EP_MIX; a.ch[0] = 1; a.N[0] = 3840; a.ldc[0] = 3840;
        a.lda[0] = 160; a.K = 160;
        a.tm[0] = tmw; a.tm[1] = tmk; a.tm[2] = tmv; a.tm[3] = tmr; a.tm[4] = tmg;
        a.x = x; a.xx = xx;
        gemm_kernel<<<dim3(30, 32, 1), 256, GEMM_DSMEM>>>(a);
    }

    // 4) grouped projections: r,k,v,g (fp32) + dw1 (half), K=768, A from mAll
    {
        GArgs a = {};
        a.A[0] = mAll + 3*768; a.B[0] = Wt_r; a.C[0] = rr; a.ep[0] = EP_NONE; a.ch[0] = 0; a.N[0] = CC; a.ldc[0] = CC; a.lda[0] = 3840;
        a.A[1] = mAll + 1*768; a.B[1] = Wt_k; a.C[1] = kk; a.ep[1] = EP_NONE; a.ch[1] = 0; a.N[1] = CC; a.ldc[1] = CC; a.lda[1] = 3840;
        a.A[2] = mAll + 2*768; a.B[2] = Wt_v; a.C[2] = vv; a.ep[2] = EP_NONE; a.ch[2] = 0; a.N[2] = CC; a.ldc[2] = CC; a.lda[2] = 3840;
        a.A[3] = mAll + 4*768; a.B[3] = Wt_g; a.C[3] = gg; a.ep[3] = EP_SILU; a.ch[3] = 0; a.N[3] = CC; a.ldc[3] = CC; a.lda[3] = 3840;
        a.A[4] = mAll + 0*768; a.B[4] = dw1t; a.C[4] = ww; a.ep[4] = EP_TANH; a.ch[4] = 1; a.N[4] = 64; a.ldc[4] = 64; a.lda[4] = 3840;
        a.K = CC;
        gemm_kernel<<<dim3(6, 32, 5), 256, GEMM_DSMEM>>>(a);
    }

    // 5) eww = exp(tdec + ww @ dw2)
    {
        GArgs a = {};
        a.A[0] = ww; a.B[0] = dw2t; a.C[0] = eww;
        a.ep[0] = EP_EXPW; a.ch[0] = 0; a.N[0] = CC; a.ldc[0] = CC;
        a.lda[0] = 64; a.K = 64;
        a.bias = tdec;
        gemm_kernel<<<dim3(6, 32, 1), 256, GEMM_DSMEM>>>(a);
    }

    // 6) WKV: intra -> scan -> inter
    wkv_intra_kernel<<<BBATCH * NHD * NCH, 256>>>(rr, kk, vv, eww, faaa, yy,
                                                  gRt, gU, gD);
    wkv_scan_kernel<<<BBATCH * NHD, 1024>>>(gU, gD, gS);
    wkv_inter_kernel<<<BBATCH * NHD * NCH, 256>>>(gRt, gS, yy);

    // 7) LayerNorm * gate -> half ln
    ln_gate_kernel<<<MM, 256>>>(yy, gg, lnw, lnb, ln);

    // 8) output projection (fp32 out)
    {
        GArgs a = {};
        a.A[0] = ln; a.B[0] = Wt_o; a.C[0] = out;
        a.ep[0] = EP_NONE; a.ch[0] = 0; a.N[0] = CC; a.ldc[0] = CC;
        a.lda[0] = CC; a.K = CC;
        gemm_kernel<<<dim3(6, 32, 1), 256, GEMM_DSMEM>>>(a);
    }

    (void)in_sizes; (void)n_in; (void)out_size;
}